// round 2
// baseline (speedup 1.0000x reference)
#include <cuda_runtime.h>
#include <cstdint>
#include <cstddef>

// Problem constants (fixed shapes for Hgnn_17394617548829)
#define N_NODESC 50000
#define N_HEDGESC 5000
#define NNZC 800000
#define IN_C 128
#define D1C 256
#define D2C 64

// ---------------------------------------------------------------------------
// Scratch (static device globals; no allocation anywhere)
// ---------------------------------------------------------------------------
__device__ float g_agg1[(size_t)N_NODESC * IN_C];   // 25.6 MB
__device__ float g_e1  [(size_t)N_HEDGESC * IN_C];  // 2.56 MB
__device__ float g_h   [(size_t)N_NODESC * D1C];    // 51.2 MB
__device__ float g_y2  [(size_t)N_NODESC * D2C];    // 12.8 MB
__device__ float g_e2  [(size_t)N_HEDGESC * D2C];   // 1.28 MB
__device__ float g_agg2[(size_t)N_NODESC * D2C];    // 12.8 MB
__device__ int   g_deg [N_NODESC];
__device__ int   g_cnt [N_HEDGESC];
__device__ float g_dinv[N_NODESC];
__device__ float g_binv[N_HEDGESC];

// ---------------------------------------------------------------------------
// Helpers
// ---------------------------------------------------------------------------
__device__ __forceinline__ void red_add_v4(float* p, float4 v) {
    asm volatile("red.global.add.v4.f32 [%0], {%1, %2, %3, %4};"
                 :: "l"(p), "f"(v.x), "f"(v.y), "f"(v.z), "f"(v.w)
                 : "memory");
}

// ---------------------------------------------------------------------------
// Zero all scratch that is accumulated into
// ---------------------------------------------------------------------------
__global__ void zero_k() {
    int i = blockIdx.x * blockDim.x + threadIdx.x;
    int stride = gridDim.x * blockDim.x;
    const float4 z = make_float4(0.f, 0.f, 0.f, 0.f);
    float4* a1 = reinterpret_cast<float4*>(g_agg1);
    for (int j = i; j < N_NODESC * IN_C / 4; j += stride) a1[j] = z;
    float4* a2 = reinterpret_cast<float4*>(g_agg2);
    for (int j = i; j < N_NODESC * D2C / 4; j += stride) a2[j] = z;
    float4* e1 = reinterpret_cast<float4*>(g_e1);
    for (int j = i; j < N_HEDGESC * IN_C / 4; j += stride) e1[j] = z;
    float4* e2 = reinterpret_cast<float4*>(g_e2);
    for (int j = i; j < N_HEDGESC * D2C / 4; j += stride) e2[j] = z;
    for (int j = i; j < N_NODESC; j += stride) g_deg[j] = 0;
    for (int j = i; j < N_HEDGESC; j += stride) g_cnt[j] = 0;
}

// ---------------------------------------------------------------------------
// Degree histograms
// ---------------------------------------------------------------------------
__global__ void __launch_bounds__(256) hist_k(const int* __restrict__ ni,
                                              const int* __restrict__ hi) {
    int i = blockIdx.x * blockDim.x + threadIdx.x;
    if (i >= NNZC) return;
    atomicAdd(&g_deg[ni[i]], 1);
    atomicAdd(&g_cnt[hi[i]], 1);
}

__global__ void __launch_bounds__(256) inv_k() {
    int i = blockIdx.x * blockDim.x + threadIdx.x;
    if (i < N_NODESC) {
        int d = g_deg[i];
        g_dinv[i] = d > 0 ? 1.0f / (float)d : 0.0f;
    }
    if (i < N_HEDGESC) {
        int c = g_cnt[i];
        g_binv[i] = c > 0 ? 1.0f / (float)c : 0.0f;
    }
}

// ---------------------------------------------------------------------------
// Aggregation passes. Warp (or half-warp pair) per edge; float4 per lane.
// ---------------------------------------------------------------------------
// node -> hyperedge, 128 channels: e1[h] += x[n]
__global__ void __launch_bounds__(256) n2h1_k(const float* __restrict__ x,
                                              const int* __restrict__ ni,
                                              const int* __restrict__ hi) {
    unsigned g = blockIdx.x * 256u + threadIdx.x;
    unsigned e = g >> 5;
    if (e >= NNZC) return;
    int lane = g & 31;
    int n = __ldg(ni + e);
    int h = __ldg(hi + e);
    float4 v = __ldg(reinterpret_cast<const float4*>(x + (size_t)n * IN_C) + lane);
    red_add_v4(g_e1 + (size_t)h * IN_C + lane * 4, v);
}

// hyperedge -> node, 128 channels (apply Binv on read): agg1[n] += e1[h] * binv[h]
__global__ void __launch_bounds__(256) h2n1_k(const int* __restrict__ ni,
                                              const int* __restrict__ hi) {
    unsigned g = blockIdx.x * 256u + threadIdx.x;
    unsigned e = g >> 5;
    if (e >= NNZC) return;
    int lane = g & 31;
    int n = __ldg(ni + e);
    int h = __ldg(hi + e);
    float bi = g_binv[h];
    float4 v = *(reinterpret_cast<const float4*>(g_e1 + (size_t)h * IN_C) + lane);
    v.x *= bi; v.y *= bi; v.z *= bi; v.w *= bi;
    red_add_v4(g_agg1 + (size_t)n * IN_C + lane * 4, v);
}

// node -> hyperedge, 64 channels: e2[h] += y2[n]   (2 edges per warp)
__global__ void __launch_bounds__(256) n2h2_k(const int* __restrict__ ni,
                                              const int* __restrict__ hi) {
    unsigned g = blockIdx.x * 256u + threadIdx.x;
    unsigned e = g >> 4;
    if (e >= NNZC) return;
    int lane = g & 15;
    int n = __ldg(ni + e);
    int h = __ldg(hi + e);
    float4 v = *(reinterpret_cast<const float4*>(g_y2 + (size_t)n * D2C) + lane);
    red_add_v4(g_e2 + (size_t)h * D2C + lane * 4, v);
}

// hyperedge -> node, 64 channels: agg2[n] += e2[h] * binv[h]
__global__ void __launch_bounds__(256) h2n2_k(const int* __restrict__ ni,
                                              const int* __restrict__ hi) {
    unsigned g = blockIdx.x * 256u + threadIdx.x;
    unsigned e = g >> 4;
    if (e >= NNZC) return;
    int lane = g & 15;
    int n = __ldg(ni + e);
    int h = __ldg(hi + e);
    float bi = g_binv[h];
    float4 v = *(reinterpret_cast<const float4*>(g_e2 + (size_t)h * D2C) + lane);
    v.x *= bi; v.y *= bi; v.z *= bi; v.w *= bi;
    red_add_v4(g_agg2 + (size_t)n * D2C + lane * 4, v);
}

// ---------------------------------------------------------------------------
// Final epilogue: out = relu(agg2 * dinv[row] + b2)
// ---------------------------------------------------------------------------
__global__ void __launch_bounds__(256) final_k(const float* __restrict__ b2,
                                               float* __restrict__ out) {
    int i = blockIdx.x * blockDim.x + threadIdx.x;  // float4 index
    if (i >= N_NODESC * D2C / 4) return;
    int n  = i / (D2C / 4);
    int c4 = i % (D2C / 4);
    float d = g_dinv[n];
    float4 a = reinterpret_cast<const float4*>(g_agg2)[i];
    float4 b = __ldg(reinterpret_cast<const float4*>(b2) + c4);
    float4 r;
    r.x = fmaxf(fmaf(a.x, d, b.x), 0.f);
    r.y = fmaxf(fmaf(a.y, d, b.y), 0.f);
    r.z = fmaxf(fmaf(a.z, d, b.z), 0.f);
    r.w = fmaxf(fmaf(a.w, d, b.w), 0.f);
    reinterpret_cast<float4*>(out)[i] = r;
}

// ---------------------------------------------------------------------------
// SIMT SGEMM: C = op(A * rowscale) @ B, optional relu(+bias) epilogue.
// BM x BN block tile, TM x TN per-thread micro-tile, (BM/TM)*(BN/TN) threads.
// ---------------------------------------------------------------------------
template <int BM, int BN, int BK, int TM, int TN, bool EPI, bool SCALE>
__device__ __forceinline__ void sgemm_body(const float* __restrict__ A,
                                           const float* __restrict__ B,
                                           const float* __restrict__ bias,
                                           const float* __restrict__ rs,
                                           float* __restrict__ C,
                                           int M, int N, int K) {
    constexpr int THREADS = (BM / TM) * (BN / TN);
    __shared__ __align__(16) float As[BK][BM + 4];
    __shared__ __align__(16) float Bs[BK][BN];

    const int tid  = threadIdx.x;
    const int row0 = blockIdx.y * BM;
    const int col0 = blockIdx.x * BN;
    const int tx   = tid % (BN / TN);
    const int ty   = tid / (BN / TN);

    float acc[TM][TN];
#pragma unroll
    for (int i = 0; i < TM; i++)
#pragma unroll
        for (int j = 0; j < TN; j++) acc[i][j] = 0.f;

    constexpr int A_VEC = (BM * BK / 4) / THREADS;
    constexpr int B_VEC = (BK * BN / 4) / THREADS;

    for (int kt = 0; kt < K; kt += BK) {
        // Load A tile (BM x BK), transposed into As, optionally row-scaled
#pragma unroll
        for (int i = 0; i < A_VEC; i++) {
            int idx = tid + i * THREADS;
            int r   = idx / (BK / 4);
            int kc  = (idx % (BK / 4)) * 4;
            int grow = row0 + r;
            float4 v = make_float4(0.f, 0.f, 0.f, 0.f);
            if (grow < M) {
                v = __ldg(reinterpret_cast<const float4*>(&A[(size_t)grow * K + kt + kc]));
                if (SCALE) {
                    float s = rs[grow];
                    v.x *= s; v.y *= s; v.z *= s; v.w *= s;
                }
            }
            As[kc + 0][r] = v.x;
            As[kc + 1][r] = v.y;
            As[kc + 2][r] = v.z;
            As[kc + 3][r] = v.w;
        }
        // Load B tile (BK x BN)
#pragma unroll
        for (int i = 0; i < B_VEC; i++) {
            int idx = tid + i * THREADS;
            int r   = idx / (BN / 4);
            int c   = (idx % (BN / 4)) * 4;
            float4 v = __ldg(reinterpret_cast<const float4*>(&B[(size_t)(kt + r) * N + col0 + c]));
            *reinterpret_cast<float4*>(&Bs[r][c]) = v;
        }
        __syncthreads();

#pragma unroll
        for (int k = 0; k < BK; k++) {
            float a[TM], b[TN];
#pragma unroll
            for (int i = 0; i < TM; i++) a[i] = As[k][ty * TM + i];
#pragma unroll
            for (int j = 0; j < TN; j++) b[j] = Bs[k][tx * TN + j];
#pragma unroll
            for (int i = 0; i < TM; i++)
#pragma unroll
                for (int j = 0; j < TN; j++) acc[i][j] = fmaf(a[i], b[j], acc[i][j]);
        }
        __syncthreads();
    }

    // Epilogue
#pragma unroll
    for (int i = 0; i < TM; i++) {
        int r = row0 + ty * TM + i;
        if (r >= M) continue;
#pragma unroll
        for (int j = 0; j < TN; j += 4) {
            int c = col0 + tx * TN + j;
            float4 v = make_float4(acc[i][j], acc[i][j + 1], acc[i][j + 2], acc[i][j + 3]);
            if (EPI) {
                v.x = fmaxf(v.x + bias[c + 0], 0.f);
                v.y = fmaxf(v.y + bias[c + 1], 0.f);
                v.z = fmaxf(v.z + bias[c + 2], 0.f);
                v.w = fmaxf(v.w + bias[c + 3], 0.f);
            }
            *reinterpret_cast<float4*>(&C[(size_t)r * N + c]) = v;
        }
    }
}

// GEMM1: g_h = relu((g_agg1 * dinv) @ W1 + b1)   [50000x128]@[128x256]
__global__ void __launch_bounds__(256) gemm1_k(const float* __restrict__ W1,
                                               const float* __restrict__ b1) {
    sgemm_body<128, 128, 16, 8, 8, true, true>(g_agg1, W1, b1, g_dinv, g_h,
                                               N_NODESC, D1C, IN_C);
}

// GEMM2: g_y2 = g_h @ W2   [50000x256]@[256x64]
__global__ void __launch_bounds__(256) gemm2_k(const float* __restrict__ W2) {
    sgemm_body<128, 64, 16, 8, 4, false, false>(g_h, W2, nullptr, nullptr, g_y2,
                                                N_NODESC, D2C, D1C);
}

// ---------------------------------------------------------------------------
// Launch
// ---------------------------------------------------------------------------
extern "C" void kernel_launch(void* const* d_in, const int* in_sizes, int n_in,
                              void* d_out, int out_size) {
    const float* x    = (const float*)d_in[0];
    const int*   edge = (const int*)d_in[1];
    const float* W1   = (const float*)d_in[2];
    const float* b1   = (const float*)d_in[3];
    const float* W2   = (const float*)d_in[4];
    const float* b2   = (const float*)d_in[5];
    float*       out  = (float*)d_out;

    const int* ni = edge;          // edge[0] = node_idx
    const int* hi = edge + NNZC;   // edge[1] = hedge_idx

    // 1. zero scratch accumulators + degree counters
    zero_k<<<4096, 256>>>();

    // 2. degrees and inverse normalizations
    hist_k<<<(NNZC + 255) / 256, 256>>>(ni, hi);
    inv_k<<<(N_NODESC + 255) / 256, 256>>>();

    // 3. layer 1 aggregation at 128 channels: agg1 = H B^-1 H^T x
    n2h1_k<<<(NNZC * 32) / 256, 256>>>(x, ni, hi);
    h2n1_k<<<(NNZC * 32) / 256, 256>>>(ni, hi);

    // 4. h = relu((agg1 * dinv) @ W1 + b1) ; y2 = h @ W2
    {
        dim3 g1(D1C / 128, (N_NODESC + 127) / 128);
        gemm1_k<<<g1, 256>>>(W1, b1);
        dim3 g2(1, (N_NODESC + 127) / 128);
        gemm2_k<<<g2, 256>>>(W2);
    }

    // 5. layer 2 aggregation at 64 channels
    n2h2_k<<<(NNZC * 16) / 256, 256>>>(ni, hi);
    h2n2_k<<<(NNZC * 16) / 256, 256>>>(ni, hi);

    // 6. out = relu(agg2 * dinv + b2)
    final_k<<<(N_NODESC * D2C / 4 + 255) / 256, 256>>>(b2, out);
}

// round 3
// speedup vs baseline: 1.0692x; 1.0692x over previous
#include <cuda_runtime.h>
#include <cstdint>
#include <cstddef>

// Problem constants (fixed shapes for Hgnn_17394617548829)
#define N_NODESC 50000
#define N_HEDGESC 5000
#define NNZC 800000
#define IN_C 128
#define D1C 256
#define D2C 64

// ---------------------------------------------------------------------------
// Scratch (static device globals; no allocation anywhere)
// ---------------------------------------------------------------------------
__device__ float g_agg1[(size_t)N_NODESC * IN_C];   // 25.6 MB
__device__ float g_e1  [(size_t)N_HEDGESC * IN_C];  // 2.56 MB
__device__ float g_h   [(size_t)N_NODESC * D1C];    // 51.2 MB
__device__ float g_y2  [(size_t)N_NODESC * D2C];    // 12.8 MB
__device__ float g_e2  [(size_t)N_HEDGESC * D2C];   // 1.28 MB
__device__ int   g_cnt [N_HEDGESC];                 // hedge degree
__device__ int   g_deg [N_NODESC];                  // node degree
__device__ int   g_hoff[N_HEDGESC + 1];             // CSR offsets (hedge-major)
__device__ int   g_noff[N_NODESC + 1];              // CSR offsets (node-major)
__device__ int   g_hcur[N_HEDGESC];                 // scatter cursors
__device__ int   g_ncur[N_NODESC];
__device__ int   g_hlist[NNZC];                     // node ids grouped by hedge
__device__ int   g_nlist[NNZC];                     // hedge ids grouped by node
__device__ float g_dinv[N_NODESC];
__device__ float g_binv[N_HEDGESC];

// ---------------------------------------------------------------------------
// 1. zero degree counters
// ---------------------------------------------------------------------------
__global__ void zero_k() {
    int i = blockIdx.x * blockDim.x + threadIdx.x;
    int stride = gridDim.x * blockDim.x;
    for (int j = i; j < N_NODESC; j += stride) g_deg[j] = 0;
    for (int j = i; j < N_HEDGESC; j += stride) g_cnt[j] = 0;
}

// ---------------------------------------------------------------------------
// 2. degree histograms
// ---------------------------------------------------------------------------
__global__ void __launch_bounds__(256) hist_k(const int* __restrict__ ni,
                                              const int* __restrict__ hi) {
    int i = blockIdx.x * blockDim.x + threadIdx.x;
    if (i >= NNZC) return;
    atomicAdd(&g_deg[ni[i]], 1);
    atomicAdd(&g_cnt[hi[i]], 1);
}

// ---------------------------------------------------------------------------
// 3. exclusive scan of both histograms (block 0: hedges, block 1: nodes)
//    Also produces inverse-degree tables and scatter cursors.
// ---------------------------------------------------------------------------
__global__ void __launch_bounds__(1024) scan_k() {
    const bool hedge = (blockIdx.x == 0);
    const int n      = hedge ? N_HEDGESC : N_NODESC;
    int*   cntarr    = hedge ? g_cnt  : g_deg;
    int*   off       = hedge ? g_hoff : g_noff;
    int*   cur       = hedge ? g_hcur : g_ncur;
    float* inv       = hedge ? g_binv : g_dinv;

    __shared__ int part[1024];
    const int tid   = threadIdx.x;
    const int chunk = (n + 1023) / 1024;
    const int b = tid * chunk;
    const int e = min(b + chunk, n);

    int s = 0;
    for (int i = b; i < e; i++) s += cntarr[i];
    part[tid] = s;
    __syncthreads();
    // inclusive Hillis-Steele scan of 1024 partials
    for (int d = 1; d < 1024; d <<= 1) {
        int v = (tid >= d) ? part[tid - d] : 0;
        __syncthreads();
        part[tid] += v;
        __syncthreads();
    }
    int run = part[tid] - s;  // exclusive prefix for this chunk
    for (int i = b; i < e; i++) {
        int c = cntarr[i];
        off[i] = run;
        cur[i] = run;
        inv[i] = (c > 0) ? 1.0f / (float)c : 0.0f;
        run += c;
    }
    if (tid == 1023) off[n] = run;
}

// ---------------------------------------------------------------------------
// 4. scatter edges into both CSR member lists
// ---------------------------------------------------------------------------
__global__ void __launch_bounds__(256) build_k(const int* __restrict__ ni,
                                               const int* __restrict__ hi) {
    int i = blockIdx.x * blockDim.x + threadIdx.x;
    if (i >= NNZC) return;
    int n = ni[i];
    int h = hi[i];
    int p = atomicAdd(&g_hcur[h], 1);
    g_hlist[p] = n;
    int q = atomicAdd(&g_ncur[n], 1);
    g_nlist[q] = h;
}

// ---------------------------------------------------------------------------
// Gather kernels (no atomics). Warp per segment (128 ch) or 16-lane group (64 ch).
// ---------------------------------------------------------------------------
// e1[h] = binv[h] * sum over members of x[n]   (128 channels, warp per hedge)
__global__ void __launch_bounds__(256) n2h1_k(const float* __restrict__ x) {
    int w = blockIdx.x * 8 + (threadIdx.x >> 5);
    if (w >= N_HEDGESC) return;
    int lane = threadIdx.x & 31;
    int base = g_hoff[w], end = g_hoff[w + 1];
    float4 acc = make_float4(0.f, 0.f, 0.f, 0.f);
    while (base + 32 <= end) {
        int m = g_hlist[base + lane];
#pragma unroll
        for (int j = 0; j < 32; j++) {
            int nid = __shfl_sync(0xffffffffu, m, j);
            float4 v = __ldg(reinterpret_cast<const float4*>(x + (size_t)nid * IN_C) + lane);
            acc.x += v.x; acc.y += v.y; acc.z += v.z; acc.w += v.w;
        }
        base += 32;
    }
    int rem = end - base;
    if (rem > 0) {
        int m = (lane < rem) ? g_hlist[base + lane] : 0;
        for (int j = 0; j < rem; j++) {
            int nid = __shfl_sync(0xffffffffu, m, j);
            float4 v = __ldg(reinterpret_cast<const float4*>(x + (size_t)nid * IN_C) + lane);
            acc.x += v.x; acc.y += v.y; acc.z += v.z; acc.w += v.w;
        }
    }
    float bi = g_binv[w];
    acc.x *= bi; acc.y *= bi; acc.z *= bi; acc.w *= bi;
    reinterpret_cast<float4*>(g_e1 + (size_t)w * IN_C)[lane] = acc;
}

// agg1[n] = dinv[n] * sum over member hedges of e1[h]  (128 ch, warp per node)
__global__ void __launch_bounds__(256) h2n1_k() {
    int w = blockIdx.x * 8 + (threadIdx.x >> 5);
    if (w >= N_NODESC) return;
    int lane = threadIdx.x & 31;
    int base = g_noff[w], end = g_noff[w + 1];
    float4 acc = make_float4(0.f, 0.f, 0.f, 0.f);
    while (base + 32 <= end) {
        int m = g_nlist[base + lane];
#pragma unroll
        for (int j = 0; j < 32; j++) {
            int hid = __shfl_sync(0xffffffffu, m, j);
            float4 v = __ldg(reinterpret_cast<const float4*>(g_e1 + (size_t)hid * IN_C) + lane);
            acc.x += v.x; acc.y += v.y; acc.z += v.z; acc.w += v.w;
        }
        base += 32;
    }
    int rem = end - base;
    if (rem > 0) {
        int m = (lane < rem) ? g_nlist[base + lane] : 0;
        for (int j = 0; j < rem; j++) {
            int hid = __shfl_sync(0xffffffffu, m, j);
            float4 v = __ldg(reinterpret_cast<const float4*>(g_e1 + (size_t)hid * IN_C) + lane);
            acc.x += v.x; acc.y += v.y; acc.z += v.z; acc.w += v.w;
        }
    }
    float di = g_dinv[w];
    acc.x *= di; acc.y *= di; acc.z *= di; acc.w *= di;
    reinterpret_cast<float4*>(g_agg1 + (size_t)w * IN_C)[lane] = acc;
}

// e2[h] = binv[h] * sum over members of y2[n]   (64 ch, 16-lane group per hedge)
__global__ void __launch_bounds__(256) n2h2_k() {
    int g = blockIdx.x * 16 + (threadIdx.x >> 4);
    if (g >= N_HEDGESC) return;
    int lane = threadIdx.x & 15;
    unsigned mask = 0xFFFFu << (threadIdx.x & 16);
    int base = g_hoff[g], end = g_hoff[g + 1];
    float4 acc = make_float4(0.f, 0.f, 0.f, 0.f);
    while (base + 16 <= end) {
        int m = g_hlist[base + lane];
#pragma unroll
        for (int j = 0; j < 16; j++) {
            int nid = __shfl_sync(mask, m, j, 16);
            float4 v = __ldg(reinterpret_cast<const float4*>(g_y2 + (size_t)nid * D2C) + lane);
            acc.x += v.x; acc.y += v.y; acc.z += v.z; acc.w += v.w;
        }
        base += 16;
    }
    int rem = end - base;
    if (rem > 0) {
        int m = (lane < rem) ? g_hlist[base + lane] : 0;
        for (int j = 0; j < rem; j++) {
            int nid = __shfl_sync(mask, m, j, 16);
            float4 v = __ldg(reinterpret_cast<const float4*>(g_y2 + (size_t)nid * D2C) + lane);
            acc.x += v.x; acc.y += v.y; acc.z += v.z; acc.w += v.w;
        }
    }
    float bi = g_binv[g];
    acc.x *= bi; acc.y *= bi; acc.z *= bi; acc.w *= bi;
    reinterpret_cast<float4*>(g_e2 + (size_t)g * D2C)[lane] = acc;
}

// out[n] = relu(dinv[n] * sum over member hedges of e2[h] + b2)  (fused epilogue)
__global__ void __launch_bounds__(256) h2n2_k(const float* __restrict__ b2,
                                              float* __restrict__ out) {
    int g = blockIdx.x * 16 + (threadIdx.x >> 4);
    if (g >= N_NODESC) return;
    int lane = threadIdx.x & 15;
    unsigned mask = 0xFFFFu << (threadIdx.x & 16);
    int base = g_noff[g], end = g_noff[g + 1];
    float4 acc = make_float4(0.f, 0.f, 0.f, 0.f);
    while (base + 16 <= end) {
        int m = g_nlist[base + lane];
#pragma unroll
        for (int j = 0; j < 16; j++) {
            int hid = __shfl_sync(mask, m, j, 16);
            float4 v = __ldg(reinterpret_cast<const float4*>(g_e2 + (size_t)hid * D2C) + lane);
            acc.x += v.x; acc.y += v.y; acc.z += v.z; acc.w += v.w;
        }
        base += 16;
    }
    int rem = end - base;
    if (rem > 0) {
        int m = (lane < rem) ? g_nlist[base + lane] : 0;
        for (int j = 0; j < rem; j++) {
            int hid = __shfl_sync(mask, m, j, 16);
            float4 v = __ldg(reinterpret_cast<const float4*>(g_e2 + (size_t)hid * D2C) + lane);
            acc.x += v.x; acc.y += v.y; acc.z += v.z; acc.w += v.w;
        }
    }
    float di = g_dinv[g];
    float4 b = __ldg(reinterpret_cast<const float4*>(b2) + lane);
    float4 r;
    r.x = fmaxf(fmaf(acc.x, di, b.x), 0.f);
    r.y = fmaxf(fmaf(acc.y, di, b.y), 0.f);
    r.z = fmaxf(fmaf(acc.z, di, b.z), 0.f);
    r.w = fmaxf(fmaf(acc.w, di, b.w), 0.f);
    reinterpret_cast<float4*>(out + (size_t)g * D2C)[lane] = r;
}

// ---------------------------------------------------------------------------
// SIMT SGEMM: C = A @ B, optional relu(+bias) epilogue.
// ---------------------------------------------------------------------------
template <int BM, int BN, int BK, int TM, int TN, bool EPI>
__device__ __forceinline__ void sgemm_body(const float* __restrict__ A,
                                           const float* __restrict__ B,
                                           const float* __restrict__ bias,
                                           float* __restrict__ C,
                                           int M, int N, int K) {
    constexpr int THREADS = (BM / TM) * (BN / TN);
    __shared__ __align__(16) float As[BK][BM + 4];
    __shared__ __align__(16) float Bs[BK][BN];

    const int tid  = threadIdx.x;
    const int row0 = blockIdx.y * BM;
    const int col0 = blockIdx.x * BN;
    const int tx   = tid % (BN / TN);
    const int ty   = tid / (BN / TN);

    float acc[TM][TN];
#pragma unroll
    for (int i = 0; i < TM; i++)
#pragma unroll
        for (int j = 0; j < TN; j++) acc[i][j] = 0.f;

    constexpr int A_VEC = (BM * BK / 4) / THREADS;
    constexpr int B_VEC = (BK * BN / 4) / THREADS;

    for (int kt = 0; kt < K; kt += BK) {
#pragma unroll
        for (int i = 0; i < A_VEC; i++) {
            int idx = tid + i * THREADS;
            int r   = idx / (BK / 4);
            int kc  = (idx % (BK / 4)) * 4;
            int grow = row0 + r;
            float4 v = make_float4(0.f, 0.f, 0.f, 0.f);
            if (grow < M)
                v = __ldg(reinterpret_cast<const float4*>(&A[(size_t)grow * K + kt + kc]));
            As[kc + 0][r] = v.x;
            As[kc + 1][r] = v.y;
            As[kc + 2][r] = v.z;
            As[kc + 3][r] = v.w;
        }
#pragma unroll
        for (int i = 0; i < B_VEC; i++) {
            int idx = tid + i * THREADS;
            int r   = idx / (BN / 4);
            int c   = (idx % (BN / 4)) * 4;
            float4 v = __ldg(reinterpret_cast<const float4*>(&B[(size_t)(kt + r) * N + col0 + c]));
            *reinterpret_cast<float4*>(&Bs[r][c]) = v;
        }
        __syncthreads();

#pragma unroll
        for (int k = 0; k < BK; k++) {
            float a[TM], b[TN];
#pragma unroll
            for (int i = 0; i < TM; i++) a[i] = As[k][ty * TM + i];
#pragma unroll
            for (int j = 0; j < TN; j++) b[j] = Bs[k][tx * TN + j];
#pragma unroll
            for (int i = 0; i < TM; i++)
#pragma unroll
                for (int j = 0; j < TN; j++) acc[i][j] = fmaf(a[i], b[j], acc[i][j]);
        }
        __syncthreads();
    }

#pragma unroll
    for (int i = 0; i < TM; i++) {
        int r = row0 + ty * TM + i;
        if (r >= M) continue;
#pragma unroll
        for (int j = 0; j < TN; j += 4) {
            int c = col0 + tx * TN + j;
            float4 v = make_float4(acc[i][j], acc[i][j + 1], acc[i][j + 2], acc[i][j + 3]);
            if (EPI) {
                v.x = fmaxf(v.x + bias[c + 0], 0.f);
                v.y = fmaxf(v.y + bias[c + 1], 0.f);
                v.z = fmaxf(v.z + bias[c + 2], 0.f);
                v.w = fmaxf(v.w + bias[c + 3], 0.f);
            }
            *reinterpret_cast<float4*>(&C[(size_t)r * N + c]) = v;
        }
    }
}

// GEMM1: g_h = relu(g_agg1 @ W1 + b1)   [50000x128]@[128x256]
__global__ void __launch_bounds__(256) gemm1_k(const float* __restrict__ W1,
                                               const float* __restrict__ b1) {
    sgemm_body<128, 128, 16, 8, 8, true>(g_agg1, W1, b1, g_h, N_NODESC, D1C, IN_C);
}

// GEMM2: g_y2 = g_h @ W2   [50000x256]@[256x64]
__global__ void __launch_bounds__(256) gemm2_k(const float* __restrict__ W2) {
    sgemm_body<128, 64, 16, 8, 4, false>(g_h, W2, nullptr, g_y2, N_NODESC, D2C, D1C);
}

// ---------------------------------------------------------------------------
// Launch
// ---------------------------------------------------------------------------
extern "C" void kernel_launch(void* const* d_in, const int* in_sizes, int n_in,
                              void* d_out, int out_size) {
    const float* x    = (const float*)d_in[0];
    const int*   edge = (const int*)d_in[1];
    const float* W1   = (const float*)d_in[2];
    const float* b1   = (const float*)d_in[3];
    const float* W2   = (const float*)d_in[4];
    const float* b2   = (const float*)d_in[5];
    float*       out  = (float*)d_out;

    const int* ni = edge;          // edge[0] = node_idx
    const int* hi = edge + NNZC;   // edge[1] = hedge_idx

    // CSR construction
    zero_k<<<128, 256>>>();
    hist_k<<<(NNZC + 255) / 256, 256>>>(ni, hi);
    scan_k<<<2, 1024>>>();
    build_k<<<(NNZC + 255) / 256, 256>>>(ni, hi);

    // Layer 1 aggregation at 128 channels (gather, no atomics)
    n2h1_k<<<(N_HEDGESC + 7) / 8, 256>>>(x);
    h2n1_k<<<(N_NODESC + 7) / 8, 256>>>();

    // h = relu(agg1 @ W1 + b1) ; y2 = h @ W2
    {
        dim3 g1(D1C / 128, (N_NODESC + 127) / 128);
        gemm1_k<<<g1, 256>>>(W1, b1);
        dim3 g2(1, (N_NODESC + 127) / 128);
        gemm2_k<<<g2, 256>>>(W2);
    }

    // Layer 2 aggregation at 64 channels (gather) + fused final epilogue
    n2h2_k<<<(N_HEDGESC + 15) / 16, 256>>>();
    h2n2_k<<<(N_NODESC + 15) / 16, 256>>>(b2, out);
}

// round 4
// speedup vs baseline: 1.3540x; 1.2664x over previous
#include <cuda_runtime.h>
#include <cstdint>
#include <cstddef>

// Problem constants (fixed shapes for Hgnn_17394617548829)
#define N_NODESC 50000
#define N_HEDGESC 5000
#define NNZC 800000
#define IN_C 128
#define D1C 256
#define D2C 64

// Scan chunking: 256 elements per block
#define NBLK_H 20    // ceil(5000/256)
#define NBLK_N 196   // ceil(50000/256)
#define NBLK   216

// ---------------------------------------------------------------------------
// Scratch (static device globals; no allocation anywhere)
// ---------------------------------------------------------------------------
__device__ float g_agg1[(size_t)N_NODESC * IN_C];   // 25.6 MB
__device__ float g_e1  [(size_t)N_HEDGESC * IN_C];  // 2.56 MB
__device__ float g_h   [(size_t)N_NODESC * D1C];    // 51.2 MB
__device__ float g_y2  [(size_t)N_NODESC * D2C];    // 12.8 MB
__device__ float g_e2  [(size_t)N_HEDGESC * D2C];   // 1.28 MB
__device__ int   g_cnt [N_HEDGESC];                 // hedge degree
__device__ int   g_deg [N_NODESC];                  // node degree
__device__ int   g_hoff[N_HEDGESC + 1];             // CSR offsets (hedge-major)
__device__ int   g_noff[N_NODESC + 1];              // CSR offsets (node-major)
__device__ int   g_hcur[N_HEDGESC];                 // scatter cursors
__device__ int   g_ncur[N_NODESC];
__device__ int   g_hlist[NNZC];                     // node ids grouped by hedge
__device__ int   g_nlist[NNZC];                     // hedge ids grouped by node
__device__ float g_dinv[N_NODESC];
__device__ float g_binv[N_HEDGESC];
__device__ int   g_part[NBLK];                      // per-chunk sums
__device__ int   g_partoff[NBLK];                   // per-chunk exclusive prefix

// ---------------------------------------------------------------------------
// 1. zero degree counters
// ---------------------------------------------------------------------------
__global__ void zero_k() {
    int i = blockIdx.x * blockDim.x + threadIdx.x;
    int stride = gridDim.x * blockDim.x;
    for (int j = i; j < N_NODESC; j += stride) g_deg[j] = 0;
    for (int j = i; j < N_HEDGESC; j += stride) g_cnt[j] = 0;
}

// ---------------------------------------------------------------------------
// 2. degree histograms (2 edges per thread, independent chains)
// ---------------------------------------------------------------------------
__global__ void __launch_bounds__(256) hist_k(const int* __restrict__ ni,
                                              const int* __restrict__ hi) {
    int i = blockIdx.x * blockDim.x + threadIdx.x;
    if (2 * i >= NNZC) return;
    int2 nn = *reinterpret_cast<const int2*>(ni + 2 * i);
    int2 hh = *reinterpret_cast<const int2*>(hi + 2 * i);
    atomicAdd(&g_deg[nn.x], 1);
    atomicAdd(&g_deg[nn.y], 1);
    atomicAdd(&g_cnt[hh.x], 1);
    atomicAdd(&g_cnt[hh.y], 1);
}

// ---------------------------------------------------------------------------
// 3a. per-chunk sums (blocks 0..19: hedge chunks, 20..215: node chunks)
// ---------------------------------------------------------------------------
__global__ void __launch_bounds__(256) psum_k() {
    __shared__ int sh[256];
    int b = blockIdx.x;
    const int* src;
    int idx, n;
    if (b < NBLK_H) { src = g_cnt; idx = b * 256 + threadIdx.x; n = N_HEDGESC; }
    else            { src = g_deg; idx = (b - NBLK_H) * 256 + threadIdx.x; n = N_NODESC; }
    int v = (idx < n) ? src[idx] : 0;
    sh[threadIdx.x] = v;
    __syncthreads();
    for (int d = 128; d > 0; d >>= 1) {
        if (threadIdx.x < d) sh[threadIdx.x] += sh[threadIdx.x + d];
        __syncthreads();
    }
    if (threadIdx.x == 0) g_part[b] = sh[0];
}

// ---------------------------------------------------------------------------
// 3b. scan the 216 chunk sums (exclusive within each array)
// ---------------------------------------------------------------------------
__global__ void __launch_bounds__(256) pscan_k() {
    __shared__ int sh[NBLK];
    int tid = threadIdx.x;
    if (tid < NBLK) sh[tid] = g_part[tid];
    __syncthreads();
    if (tid == 0) {
        int run = 0;
        for (int i = 0; i < NBLK_H; i++) { int c = sh[i]; sh[i] = run; run += c; }
        run = 0;
        for (int i = NBLK_H; i < NBLK; i++) { int c = sh[i]; sh[i] = run; run += c; }
    }
    __syncthreads();
    if (tid < NBLK) g_partoff[tid] = sh[tid];
}

// ---------------------------------------------------------------------------
// 3c. fill offsets / cursors / inverse degrees (block exclusive scan + base)
// ---------------------------------------------------------------------------
__global__ void __launch_bounds__(256) fill_k() {
    __shared__ int sh[256];
    int b = blockIdx.x;
    int tid = threadIdx.x;
    const int* src; int* off; int* cur; float* inv;
    int idx, n;
    if (b < NBLK_H) {
        src = g_cnt; off = g_hoff; cur = g_hcur; inv = g_binv;
        idx = b * 256 + tid; n = N_HEDGESC;
    } else {
        src = g_deg; off = g_noff; cur = g_ncur; inv = g_dinv;
        idx = (b - NBLK_H) * 256 + tid; n = N_NODESC;
    }
    int v = (idx < n) ? src[idx] : 0;
    sh[tid] = v;
    __syncthreads();
    // Hillis-Steele inclusive scan
    for (int d = 1; d < 256; d <<= 1) {
        int t = (tid >= d) ? sh[tid - d] : 0;
        __syncthreads();
        sh[tid] += t;
        __syncthreads();
    }
    if (idx < n) {
        int excl = sh[tid] - v + g_partoff[b];
        off[idx] = excl;
        cur[idx] = excl;
        inv[idx] = (v > 0) ? 1.0f / (float)v : 0.0f;
    }
    if (b == 0 && tid == 0) {
        g_hoff[N_HEDGESC] = NNZC;
        g_noff[N_NODESC]  = NNZC;
    }
}

// ---------------------------------------------------------------------------
// 4. scatter edges into both CSR member lists (2 edges per thread)
// ---------------------------------------------------------------------------
__global__ void __launch_bounds__(256) build_k(const int* __restrict__ ni,
                                               const int* __restrict__ hi) {
    int i = blockIdx.x * blockDim.x + threadIdx.x;
    if (2 * i >= NNZC) return;
    int2 nn = *reinterpret_cast<const int2*>(ni + 2 * i);
    int2 hh = *reinterpret_cast<const int2*>(hi + 2 * i);
    int p0 = atomicAdd(&g_hcur[hh.x], 1);
    int p1 = atomicAdd(&g_hcur[hh.y], 1);
    int q0 = atomicAdd(&g_ncur[nn.x], 1);
    int q1 = atomicAdd(&g_ncur[nn.y], 1);
    g_hlist[p0] = nn.x;
    g_hlist[p1] = nn.y;
    g_nlist[q0] = hh.x;
    g_nlist[q1] = hh.y;
}

// ---------------------------------------------------------------------------
// Gather kernels (no atomics, no shuffles — indices are group-uniform).
// ---------------------------------------------------------------------------
// e1[h] = binv[h] * sum over members of x[n]   (128 channels, warp per hedge)
__global__ void __launch_bounds__(256) n2h1_k(const float* __restrict__ x) {
    int w = blockIdx.x * 8 + (threadIdx.x >> 5);
    if (w >= N_HEDGESC) return;
    int lane = threadIdx.x & 31;
    int base = g_hoff[w], end = g_hoff[w + 1];
    float4 a0 = make_float4(0.f, 0.f, 0.f, 0.f);
    float4 a1 = make_float4(0.f, 0.f, 0.f, 0.f);
    int j = base;
    for (; j + 4 <= end; j += 4) {
        int n0 = __ldg(g_hlist + j + 0);
        int n1 = __ldg(g_hlist + j + 1);
        int n2 = __ldg(g_hlist + j + 2);
        int n3 = __ldg(g_hlist + j + 3);
        float4 v0 = __ldg(reinterpret_cast<const float4*>(x + (size_t)n0 * IN_C) + lane);
        float4 v1 = __ldg(reinterpret_cast<const float4*>(x + (size_t)n1 * IN_C) + lane);
        float4 v2 = __ldg(reinterpret_cast<const float4*>(x + (size_t)n2 * IN_C) + lane);
        float4 v3 = __ldg(reinterpret_cast<const float4*>(x + (size_t)n3 * IN_C) + lane);
        a0.x += v0.x; a0.y += v0.y; a0.z += v0.z; a0.w += v0.w;
        a1.x += v1.x; a1.y += v1.y; a1.z += v1.z; a1.w += v1.w;
        a0.x += v2.x; a0.y += v2.y; a0.z += v2.z; a0.w += v2.w;
        a1.x += v3.x; a1.y += v3.y; a1.z += v3.z; a1.w += v3.w;
    }
    for (; j < end; j++) {
        int n0 = __ldg(g_hlist + j);
        float4 v0 = __ldg(reinterpret_cast<const float4*>(x + (size_t)n0 * IN_C) + lane);
        a0.x += v0.x; a0.y += v0.y; a0.z += v0.z; a0.w += v0.w;
    }
    float bi = g_binv[w];
    float4 r;
    r.x = (a0.x + a1.x) * bi;
    r.y = (a0.y + a1.y) * bi;
    r.z = (a0.z + a1.z) * bi;
    r.w = (a0.w + a1.w) * bi;
    reinterpret_cast<float4*>(g_e1 + (size_t)w * IN_C)[lane] = r;
}

// agg1[n] = dinv[n] * sum over member hedges of e1[h]  (128 ch, warp per node)
__global__ void __launch_bounds__(256) h2n1_k() {
    int w = blockIdx.x * 8 + (threadIdx.x >> 5);
    if (w >= N_NODESC) return;
    int lane = threadIdx.x & 31;
    int base = g_noff[w], end = g_noff[w + 1];
    float4 a0 = make_float4(0.f, 0.f, 0.f, 0.f);
    float4 a1 = make_float4(0.f, 0.f, 0.f, 0.f);
    int j = base;
    for (; j + 4 <= end; j += 4) {
        int h0 = __ldg(g_nlist + j + 0);
        int h1 = __ldg(g_nlist + j + 1);
        int h2 = __ldg(g_nlist + j + 2);
        int h3 = __ldg(g_nlist + j + 3);
        float4 v0 = __ldg(reinterpret_cast<const float4*>(g_e1 + (size_t)h0 * IN_C) + lane);
        float4 v1 = __ldg(reinterpret_cast<const float4*>(g_e1 + (size_t)h1 * IN_C) + lane);
        float4 v2 = __ldg(reinterpret_cast<const float4*>(g_e1 + (size_t)h2 * IN_C) + lane);
        float4 v3 = __ldg(reinterpret_cast<const float4*>(g_e1 + (size_t)h3 * IN_C) + lane);
        a0.x += v0.x; a0.y += v0.y; a0.z += v0.z; a0.w += v0.w;
        a1.x += v1.x; a1.y += v1.y; a1.z += v1.z; a1.w += v1.w;
        a0.x += v2.x; a0.y += v2.y; a0.z += v2.z; a0.w += v2.w;
        a1.x += v3.x; a1.y += v3.y; a1.z += v3.z; a1.w += v3.w;
    }
    for (; j < end; j++) {
        int h0 = __ldg(g_nlist + j);
        float4 v0 = __ldg(reinterpret_cast<const float4*>(g_e1 + (size_t)h0 * IN_C) + lane);
        a0.x += v0.x; a0.y += v0.y; a0.z += v0.z; a0.w += v0.w;
    }
    float di = g_dinv[w];
    float4 r;
    r.x = (a0.x + a1.x) * di;
    r.y = (a0.y + a1.y) * di;
    r.z = (a0.z + a1.z) * di;
    r.w = (a0.w + a1.w) * di;
    reinterpret_cast<float4*>(g_agg1 + (size_t)w * IN_C)[lane] = r;
}

// e2[h] = binv[h] * sum over members of y2[n]   (64 ch, 16-lane group per hedge)
__global__ void __launch_bounds__(256) n2h2_k() {
    int g = blockIdx.x * 16 + (threadIdx.x >> 4);
    if (g >= N_HEDGESC) return;
    int lane = threadIdx.x & 15;
    int base = g_hoff[g], end = g_hoff[g + 1];
    float4 a0 = make_float4(0.f, 0.f, 0.f, 0.f);
    float4 a1 = make_float4(0.f, 0.f, 0.f, 0.f);
    int j = base;
    for (; j + 4 <= end; j += 4) {
        int n0 = __ldg(g_hlist + j + 0);
        int n1 = __ldg(g_hlist + j + 1);
        int n2 = __ldg(g_hlist + j + 2);
        int n3 = __ldg(g_hlist + j + 3);
        float4 v0 = __ldg(reinterpret_cast<const float4*>(g_y2 + (size_t)n0 * D2C) + lane);
        float4 v1 = __ldg(reinterpret_cast<const float4*>(g_y2 + (size_t)n1 * D2C) + lane);
        float4 v2 = __ldg(reinterpret_cast<const float4*>(g_y2 + (size_t)n2 * D2C) + lane);
        float4 v3 = __ldg(reinterpret_cast<const float4*>(g_y2 + (size_t)n3 * D2C) + lane);
        a0.x += v0.x; a0.y += v0.y; a0.z += v0.z; a0.w += v0.w;
        a1.x += v1.x; a1.y += v1.y; a1.z += v1.z; a1.w += v1.w;
        a0.x += v2.x; a0.y += v2.y; a0.z += v2.z; a0.w += v2.w;
        a1.x += v3.x; a1.y += v3.y; a1.z += v3.z; a1.w += v3.w;
    }
    for (; j < end; j++) {
        int n0 = __ldg(g_hlist + j);
        float4 v0 = __ldg(reinterpret_cast<const float4*>(g_y2 + (size_t)n0 * D2C) + lane);
        a0.x += v0.x; a0.y += v0.y; a0.z += v0.z; a0.w += v0.w;
    }
    float bi = g_binv[g];
    float4 r;
    r.x = (a0.x + a1.x) * bi;
    r.y = (a0.y + a1.y) * bi;
    r.z = (a0.z + a1.z) * bi;
    r.w = (a0.w + a1.w) * bi;
    reinterpret_cast<float4*>(g_e2 + (size_t)g * D2C)[lane] = r;
}

// out[n] = relu(dinv[n] * sum over member hedges of e2[h] + b2)  (fused epilogue)
__global__ void __launch_bounds__(256) h2n2_k(const float* __restrict__ b2,
                                              float* __restrict__ out) {
    int g = blockIdx.x * 16 + (threadIdx.x >> 4);
    if (g >= N_NODESC) return;
    int lane = threadIdx.x & 15;
    int base = g_noff[g], end = g_noff[g + 1];
    float4 a0 = make_float4(0.f, 0.f, 0.f, 0.f);
    float4 a1 = make_float4(0.f, 0.f, 0.f, 0.f);
    int j = base;
    for (; j + 4 <= end; j += 4) {
        int h0 = __ldg(g_nlist + j + 0);
        int h1 = __ldg(g_nlist + j + 1);
        int h2 = __ldg(g_nlist + j + 2);
        int h3 = __ldg(g_nlist + j + 3);
        float4 v0 = __ldg(reinterpret_cast<const float4*>(g_e2 + (size_t)h0 * D2C) + lane);
        float4 v1 = __ldg(reinterpret_cast<const float4*>(g_e2 + (size_t)h1 * D2C) + lane);
        float4 v2 = __ldg(reinterpret_cast<const float4*>(g_e2 + (size_t)h2 * D2C) + lane);
        float4 v3 = __ldg(reinterpret_cast<const float4*>(g_e2 + (size_t)h3 * D2C) + lane);
        a0.x += v0.x; a0.y += v0.y; a0.z += v0.z; a0.w += v0.w;
        a1.x += v1.x; a1.y += v1.y; a1.z += v1.z; a1.w += v1.w;
        a0.x += v2.x; a0.y += v2.y; a0.z += v2.z; a0.w += v2.w;
        a1.x += v3.x; a1.y += v3.y; a1.z += v3.z; a1.w += v3.w;
    }
    for (; j < end; j++) {
        int h0 = __ldg(g_nlist + j);
        float4 v0 = __ldg(reinterpret_cast<const float4*>(g_e2 + (size_t)h0 * D2C) + lane);
        a0.x += v0.x; a0.y += v0.y; a0.z += v0.z; a0.w += v0.w;
    }
    float di = g_dinv[g];
    float4 b = __ldg(reinterpret_cast<const float4*>(b2) + lane);
    float4 r;
    r.x = fmaxf(fmaf(a0.x + a1.x, di, b.x), 0.f);
    r.y = fmaxf(fmaf(a0.y + a1.y, di, b.y), 0.f);
    r.z = fmaxf(fmaf(a0.z + a1.z, di, b.z), 0.f);
    r.w = fmaxf(fmaf(a0.w + a1.w, di, b.w), 0.f);
    reinterpret_cast<float4*>(out + (size_t)g * D2C)[lane] = r;
}

// ---------------------------------------------------------------------------
// SIMT SGEMM, double-buffered (2-stage smem + register staging, 1 sync/tile).
// ---------------------------------------------------------------------------
template <int BM, int BN, int BK, int TM, int TN, bool EPI>
__device__ __forceinline__ void sgemm_body(const float* __restrict__ A,
                                           const float* __restrict__ B,
                                           const float* __restrict__ bias,
                                           float* __restrict__ C,
                                           int M, int N, int K) {
    constexpr int THREADS = (BM / TM) * (BN / TN);
    constexpr int AV = (BM * BK / 4) / THREADS;
    constexpr int BV = (BK * BN / 4) / THREADS;
    __shared__ __align__(16) float As[2][BK][BM + 4];
    __shared__ __align__(16) float Bs[2][BK][BN];

    const int tid  = threadIdx.x;
    const int row0 = blockIdx.y * BM;
    const int col0 = blockIdx.x * BN;
    const int tx   = tid % (BN / TN);
    const int ty   = tid / (BN / TN);

    float acc[TM][TN];
#pragma unroll
    for (int i = 0; i < TM; i++)
#pragma unroll
        for (int j = 0; j < TN; j++) acc[i][j] = 0.f;

    float4 rA[AV], rB[BV];

    // ---- load tile 0 directly to smem stage 0 ----
#pragma unroll
    for (int i = 0; i < AV; i++) {
        int idx = tid + i * THREADS;
        int rr  = idx / (BK / 4);
        int kc  = (idx % (BK / 4)) * 4;
        int grow = row0 + rr;
        float4 v = make_float4(0.f, 0.f, 0.f, 0.f);
        if (grow < M) v = __ldg(reinterpret_cast<const float4*>(&A[(size_t)grow * K + kc]));
        As[0][kc + 0][rr] = v.x;
        As[0][kc + 1][rr] = v.y;
        As[0][kc + 2][rr] = v.z;
        As[0][kc + 3][rr] = v.w;
    }
#pragma unroll
    for (int i = 0; i < BV; i++) {
        int idx = tid + i * THREADS;
        int rr  = idx / (BN / 4);
        int c   = (idx % (BN / 4)) * 4;
        float4 v = __ldg(reinterpret_cast<const float4*>(&B[(size_t)rr * N + col0 + c]));
        *reinterpret_cast<float4*>(&Bs[0][rr][c]) = v;
    }
    __syncthreads();

    const int nk = K / BK;
    for (int t = 0; t < nk; t++) {
        const int cur = t & 1, nxt = cur ^ 1;
        // prefetch next tile into registers
        if (t + 1 < nk) {
            const int kt = (t + 1) * BK;
#pragma unroll
            for (int i = 0; i < AV; i++) {
                int idx = tid + i * THREADS;
                int rr  = idx / (BK / 4);
                int kc  = (idx % (BK / 4)) * 4;
                int grow = row0 + rr;
                rA[i] = make_float4(0.f, 0.f, 0.f, 0.f);
                if (grow < M) rA[i] = __ldg(reinterpret_cast<const float4*>(&A[(size_t)grow * K + kt + kc]));
            }
#pragma unroll
            for (int i = 0; i < BV; i++) {
                int idx = tid + i * THREADS;
                int rr  = idx / (BN / 4);
                int c   = (idx % (BN / 4)) * 4;
                rB[i] = __ldg(reinterpret_cast<const float4*>(&B[(size_t)(kt + rr) * N + col0 + c]));
            }
        }
        // compute current tile
#pragma unroll
        for (int k = 0; k < BK; k++) {
            float a[TM], b[TN];
#pragma unroll
            for (int i = 0; i < TM; i++) a[i] = As[cur][k][ty * TM + i];
#pragma unroll
            for (int j = 0; j < TN; j++) b[j] = Bs[cur][k][tx * TN + j];
#pragma unroll
            for (int i = 0; i < TM; i++)
#pragma unroll
                for (int j = 0; j < TN; j++) acc[i][j] = fmaf(a[i], b[j], acc[i][j]);
        }
        // store staged regs into next buffer
        if (t + 1 < nk) {
#pragma unroll
            for (int i = 0; i < AV; i++) {
                int idx = tid + i * THREADS;
                int rr  = idx / (BK / 4);
                int kc  = (idx % (BK / 4)) * 4;
                As[nxt][kc + 0][rr] = rA[i].x;
                As[nxt][kc + 1][rr] = rA[i].y;
                As[nxt][kc + 2][rr] = rA[i].z;
                As[nxt][kc + 3][rr] = rA[i].w;
            }
#pragma unroll
            for (int i = 0; i < BV; i++) {
                int idx = tid + i * THREADS;
                int rr  = idx / (BN / 4);
                int c   = (idx % (BN / 4)) * 4;
                *reinterpret_cast<float4*>(&Bs[nxt][rr][c]) = rB[i];
            }
            __syncthreads();
        }
    }

    // Epilogue
#pragma unroll
    for (int i = 0; i < TM; i++) {
        int r = row0 + ty * TM + i;
        if (r >= M) continue;
#pragma unroll
        for (int j = 0; j < TN; j += 4) {
            int c = col0 + tx * TN + j;
            float4 v = make_float4(acc[i][j], acc[i][j + 1], acc[i][j + 2], acc[i][j + 3]);
            if (EPI) {
                v.x = fmaxf(v.x + bias[c + 0], 0.f);
                v.y = fmaxf(v.y + bias[c + 1], 0.f);
                v.z = fmaxf(v.z + bias[c + 2], 0.f);
                v.w = fmaxf(v.w + bias[c + 3], 0.f);
            }
            *reinterpret_cast<float4*>(&C[(size_t)r * N + c]) = v;
        }
    }
}

// GEMM1: g_h = relu(g_agg1 @ W1 + b1)   [50000x128]@[128x256]
__global__ void __launch_bounds__(256) gemm1_k(const float* __restrict__ W1,
                                               const float* __restrict__ b1) {
    sgemm_body<128, 128, 16, 8, 8, true>(g_agg1, W1, b1, g_h, N_NODESC, D1C, IN_C);
}

// GEMM2: g_y2 = g_h @ W2   [50000x256]@[256x64]
__global__ void __launch_bounds__(256) gemm2_k(const float* __restrict__ W2) {
    sgemm_body<128, 64, 16, 8, 4, false>(g_h, W2, nullptr, g_y2, N_NODESC, D2C, D1C);
}

// ---------------------------------------------------------------------------
// Launch
// ---------------------------------------------------------------------------
extern "C" void kernel_launch(void* const* d_in, const int* in_sizes, int n_in,
                              void* d_out, int out_size) {
    const float* x    = (const float*)d_in[0];
    const int*   edge = (const int*)d_in[1];
    const float* W1   = (const float*)d_in[2];
    const float* b1   = (const float*)d_in[3];
    const float* W2   = (const float*)d_in[4];
    const float* b2   = (const float*)d_in[5];
    float*       out  = (float*)d_out;

    const int* ni = edge;          // edge[0] = node_idx
    const int* hi = edge + NNZC;   // edge[1] = hedge_idx

    // CSR construction
    zero_k<<<256, 256>>>();
    hist_k<<<(NNZC / 2 + 255) / 256, 256>>>(ni, hi);
    psum_k<<<NBLK, 256>>>();
    pscan_k<<<1, 256>>>();
    fill_k<<<NBLK, 256>>>();
    build_k<<<(NNZC / 2 + 255) / 256, 256>>>(ni, hi);

    // Layer 1 aggregation at 128 channels (gather, no atomics)
    n2h1_k<<<(N_HEDGESC + 7) / 8, 256>>>(x);
    h2n1_k<<<(N_NODESC + 7) / 8, 256>>>();

    // h = relu(agg1 @ W1 + b1) ; y2 = h @ W2
    {
        dim3 g1(D1C / 128, (N_NODESC + 127) / 128);
        gemm1_k<<<g1, 256>>>(W1, b1);
        dim3 g2(1, (N_NODESC + 127) / 128);
        gemm2_k<<<g2, 256>>>(W2);
    }

    // Layer 2 aggregation at 64 channels (gather) + fused final epilogue
    n2h2_k<<<(N_HEDGESC + 15) / 16, 256>>>();
    h2n2_k<<<(N_NODESC + 15) / 16, 256>>>(b2, out);
}

// round 6
// speedup vs baseline: 1.6734x; 1.2359x over previous
#include <cuda_runtime.h>
#include <cstdint>
#include <cstddef>

// Problem constants (fixed shapes for Hgnn_17394617548829)
#define N_NODESC 50000
#define N_HEDGESC 5000
#define NNZC 800000
#define IN_C 128
#define D1C 256
#define D2C 64

// Scan chunking: 256 elements per block
#define NBLK_H 20    // ceil(5000/256)
#define NBLK_N 196   // ceil(50000/256)
#define NBLK   216

// ---------------------------------------------------------------------------
// Scratch (static device globals; no allocation anywhere)
// ---------------------------------------------------------------------------
__device__ float g_agg1[(size_t)N_NODESC * IN_C];   // 25.6 MB
__device__ float g_e1  [(size_t)N_HEDGESC * IN_C];  // 2.56 MB
__device__ float g_h   [(size_t)N_NODESC * D1C];    // 51.2 MB
__device__ float g_y2  [(size_t)N_NODESC * D2C];    // 12.8 MB
__device__ float g_e2  [(size_t)N_HEDGESC * D2C];   // 1.28 MB
__device__ int   g_cnt [N_HEDGESC];                 // hedge degree
__device__ int   g_deg [N_NODESC];                  // node degree
__device__ int   g_hoff[N_HEDGESC + 1];             // CSR offsets (hedge-major)
__device__ int   g_noff[N_NODESC + 1];              // CSR offsets (node-major)
__device__ int   g_hcur[N_HEDGESC];                 // scatter cursors
__device__ int   g_ncur[N_NODESC];
__device__ int   g_hlist[NNZC];                     // node ids grouped by hedge
__device__ int   g_nlist[NNZC];                     // hedge ids grouped by node
__device__ float g_dinv[N_NODESC];
__device__ float g_binv[N_HEDGESC];
__device__ int   g_part[NBLK];                      // per-chunk sums
__device__ int   g_partoff[NBLK];                   // per-chunk exclusive prefix

// ---------------------------------------------------------------------------
// 1. zero degree counters
// ---------------------------------------------------------------------------
__global__ void zero_k() {
    int i = blockIdx.x * blockDim.x + threadIdx.x;
    int stride = gridDim.x * blockDim.x;
    for (int j = i; j < N_NODESC; j += stride) g_deg[j] = 0;
    for (int j = i; j < N_HEDGESC; j += stride) g_cnt[j] = 0;
}

// ---------------------------------------------------------------------------
// 2. degree histograms (2 edges per thread, independent chains)
// ---------------------------------------------------------------------------
__global__ void __launch_bounds__(256) hist_k(const int* __restrict__ ni,
                                              const int* __restrict__ hi) {
    int i = blockIdx.x * blockDim.x + threadIdx.x;
    if (2 * i >= NNZC) return;
    int2 nn = *reinterpret_cast<const int2*>(ni + 2 * i);
    int2 hh = *reinterpret_cast<const int2*>(hi + 2 * i);
    atomicAdd(&g_deg[nn.x], 1);
    atomicAdd(&g_deg[nn.y], 1);
    atomicAdd(&g_cnt[hh.x], 1);
    atomicAdd(&g_cnt[hh.y], 1);
}

// ---------------------------------------------------------------------------
// 3a. per-chunk sums (blocks 0..19: hedge chunks, 20..215: node chunks)
// ---------------------------------------------------------------------------
__global__ void __launch_bounds__(256) psum_k() {
    __shared__ int sh[256];
    int b = blockIdx.x;
    const int* src;
    int idx, n;
    if (b < NBLK_H) { src = g_cnt; idx = b * 256 + threadIdx.x; n = N_HEDGESC; }
    else            { src = g_deg; idx = (b - NBLK_H) * 256 + threadIdx.x; n = N_NODESC; }
    int v = (idx < n) ? src[idx] : 0;
    sh[threadIdx.x] = v;
    __syncthreads();
    for (int d = 128; d > 0; d >>= 1) {
        if (threadIdx.x < d) sh[threadIdx.x] += sh[threadIdx.x + d];
        __syncthreads();
    }
    if (threadIdx.x == 0) g_part[b] = sh[0];
}

// ---------------------------------------------------------------------------
// 3b. scan the 216 chunk sums (exclusive within each array)
// ---------------------------------------------------------------------------
__global__ void __launch_bounds__(256) pscan_k() {
    __shared__ int sh[NBLK];
    int tid = threadIdx.x;
    if (tid < NBLK) sh[tid] = g_part[tid];
    __syncthreads();
    if (tid == 0) {
        int run = 0;
        for (int i = 0; i < NBLK_H; i++) { int c = sh[i]; sh[i] = run; run += c; }
        run = 0;
        for (int i = NBLK_H; i < NBLK; i++) { int c = sh[i]; sh[i] = run; run += c; }
    }
    __syncthreads();
    if (tid < NBLK) g_partoff[tid] = sh[tid];
}

// ---------------------------------------------------------------------------
// 3c. fill offsets / cursors / inverse degrees (block exclusive scan + base)
// ---------------------------------------------------------------------------
__global__ void __launch_bounds__(256) fill_k() {
    __shared__ int sh[256];
    int b = blockIdx.x;
    int tid = threadIdx.x;
    const int* src; int* off; int* cur; float* inv;
    int idx, n;
    if (b < NBLK_H) {
        src = g_cnt; off = g_hoff; cur = g_hcur; inv = g_binv;
        idx = b * 256 + tid; n = N_HEDGESC;
    } else {
        src = g_deg; off = g_noff; cur = g_ncur; inv = g_dinv;
        idx = (b - NBLK_H) * 256 + tid; n = N_NODESC;
    }
    int v = (idx < n) ? src[idx] : 0;
    sh[tid] = v;
    __syncthreads();
    // Hillis-Steele inclusive scan
    for (int d = 1; d < 256; d <<= 1) {
        int t = (tid >= d) ? sh[tid - d] : 0;
        __syncthreads();
        sh[tid] += t;
        __syncthreads();
    }
    if (idx < n) {
        int excl = sh[tid] - v + g_partoff[b];
        off[idx] = excl;
        cur[idx] = excl;
        inv[idx] = (v > 0) ? 1.0f / (float)v : 0.0f;
    }
    if (b == 0 && tid == 0) {
        g_hoff[N_HEDGESC] = NNZC;
        g_noff[N_NODESC]  = NNZC;
    }
}

// ---------------------------------------------------------------------------
// 4. scatter edges into both CSR member lists (2 edges per thread)
// ---------------------------------------------------------------------------
__global__ void __launch_bounds__(256) build_k(const int* __restrict__ ni,
                                               const int* __restrict__ hi) {
    int i = blockIdx.x * blockDim.x + threadIdx.x;
    if (2 * i >= NNZC) return;
    int2 nn = *reinterpret_cast<const int2*>(ni + 2 * i);
    int2 hh = *reinterpret_cast<const int2*>(hi + 2 * i);
    int p0 = atomicAdd(&g_hcur[hh.x], 1);
    int p1 = atomicAdd(&g_hcur[hh.y], 1);
    int q0 = atomicAdd(&g_ncur[nn.x], 1);
    int q1 = atomicAdd(&g_ncur[nn.y], 1);
    g_hlist[p0] = nn.x;
    g_hlist[p1] = nn.y;
    g_nlist[q0] = hh.x;
    g_nlist[q1] = hh.y;
}

// ---------------------------------------------------------------------------
// Gather kernels (no atomics, no shuffles — indices are group-uniform).
// ---------------------------------------------------------------------------
// e1[h] = binv[h] * sum over members of x[n]   (128 channels, warp per hedge)
__global__ void __launch_bounds__(256) n2h1_k(const float* __restrict__ x) {
    int w = blockIdx.x * 8 + (threadIdx.x >> 5);
    if (w >= N_HEDGESC) return;
    int lane = threadIdx.x & 31;
    int base = g_hoff[w], end = g_hoff[w + 1];
    float4 a0 = make_float4(0.f, 0.f, 0.f, 0.f);
    float4 a1 = make_float4(0.f, 0.f, 0.f, 0.f);
    int j = base;
    for (; j + 4 <= end; j += 4) {
        int n0 = __ldg(g_hlist + j + 0);
        int n1 = __ldg(g_hlist + j + 1);
        int n2 = __ldg(g_hlist + j + 2);
        int n3 = __ldg(g_hlist + j + 3);
        float4 v0 = __ldg(reinterpret_cast<const float4*>(x + (size_t)n0 * IN_C) + lane);
        float4 v1 = __ldg(reinterpret_cast<const float4*>(x + (size_t)n1 * IN_C) + lane);
        float4 v2 = __ldg(reinterpret_cast<const float4*>(x + (size_t)n2 * IN_C) + lane);
        float4 v3 = __ldg(reinterpret_cast<const float4*>(x + (size_t)n3 * IN_C) + lane);
        a0.x += v0.x; a0.y += v0.y; a0.z += v0.z; a0.w += v0.w;
        a1.x += v1.x; a1.y += v1.y; a1.z += v1.z; a1.w += v1.w;
        a0.x += v2.x; a0.y += v2.y; a0.z += v2.z; a0.w += v2.w;
        a1.x += v3.x; a1.y += v3.y; a1.z += v3.z; a1.w += v3.w;
    }
    for (; j < end; j++) {
        int n0 = __ldg(g_hlist + j);
        float4 v0 = __ldg(reinterpret_cast<const float4*>(x + (size_t)n0 * IN_C) + lane);
        a0.x += v0.x; a0.y += v0.y; a0.z += v0.z; a0.w += v0.w;
    }
    float bi = g_binv[w];
    float4 r;
    r.x = (a0.x + a1.x) * bi;
    r.y = (a0.y + a1.y) * bi;
    r.z = (a0.z + a1.z) * bi;
    r.w = (a0.w + a1.w) * bi;
    reinterpret_cast<float4*>(g_e1 + (size_t)w * IN_C)[lane] = r;
}

// agg1[n] = dinv[n] * sum over member hedges of e1[h]  (128 ch, warp per node)
__global__ void __launch_bounds__(256) h2n1_k() {
    int w = blockIdx.x * 8 + (threadIdx.x >> 5);
    if (w >= N_NODESC) return;
    int lane = threadIdx.x & 31;
    int base = g_noff[w], end = g_noff[w + 1];
    float4 a0 = make_float4(0.f, 0.f, 0.f, 0.f);
    float4 a1 = make_float4(0.f, 0.f, 0.f, 0.f);
    int j = base;
    for (; j + 4 <= end; j += 4) {
        int h0 = __ldg(g_nlist + j + 0);
        int h1 = __ldg(g_nlist + j + 1);
        int h2 = __ldg(g_nlist + j + 2);
        int h3 = __ldg(g_nlist + j + 3);
        float4 v0 = __ldg(reinterpret_cast<const float4*>(g_e1 + (size_t)h0 * IN_C) + lane);
        float4 v1 = __ldg(reinterpret_cast<const float4*>(g_e1 + (size_t)h1 * IN_C) + lane);
        float4 v2 = __ldg(reinterpret_cast<const float4*>(g_e1 + (size_t)h2 * IN_C) + lane);
        float4 v3 = __ldg(reinterpret_cast<const float4*>(g_e1 + (size_t)h3 * IN_C) + lane);
        a0.x += v0.x; a0.y += v0.y; a0.z += v0.z; a0.w += v0.w;
        a1.x += v1.x; a1.y += v1.y; a1.z += v1.z; a1.w += v1.w;
        a0.x += v2.x; a0.y += v2.y; a0.z += v2.z; a0.w += v2.w;
        a1.x += v3.x; a1.y += v3.y; a1.z += v3.z; a1.w += v3.w;
    }
    for (; j < end; j++) {
        int h0 = __ldg(g_nlist + j);
        float4 v0 = __ldg(reinterpret_cast<const float4*>(g_e1 + (size_t)h0 * IN_C) + lane);
        a0.x += v0.x; a0.y += v0.y; a0.z += v0.z; a0.w += v0.w;
    }
    float di = g_dinv[w];
    float4 r;
    r.x = (a0.x + a1.x) * di;
    r.y = (a0.y + a1.y) * di;
    r.z = (a0.z + a1.z) * di;
    r.w = (a0.w + a1.w) * di;
    reinterpret_cast<float4*>(g_agg1 + (size_t)w * IN_C)[lane] = r;
}

// e2[h] = binv[h] * sum over members of y2[n]   (64 ch, 16-lane group per hedge)
__global__ void __launch_bounds__(256) n2h2_k() {
    int g = blockIdx.x * 16 + (threadIdx.x >> 4);
    if (g >= N_HEDGESC) return;
    int lane = threadIdx.x & 15;
    int base = g_hoff[g], end = g_hoff[g + 1];
    float4 a0 = make_float4(0.f, 0.f, 0.f, 0.f);
    float4 a1 = make_float4(0.f, 0.f, 0.f, 0.f);
    int j = base;
    for (; j + 4 <= end; j += 4) {
        int n0 = __ldg(g_hlist + j + 0);
        int n1 = __ldg(g_hlist + j + 1);
        int n2 = __ldg(g_hlist + j + 2);
        int n3 = __ldg(g_hlist + j + 3);
        float4 v0 = __ldg(reinterpret_cast<const float4*>(g_y2 + (size_t)n0 * D2C) + lane);
        float4 v1 = __ldg(reinterpret_cast<const float4*>(g_y2 + (size_t)n1 * D2C) + lane);
        float4 v2 = __ldg(reinterpret_cast<const float4*>(g_y2 + (size_t)n2 * D2C) + lane);
        float4 v3 = __ldg(reinterpret_cast<const float4*>(g_y2 + (size_t)n3 * D2C) + lane);
        a0.x += v0.x; a0.y += v0.y; a0.z += v0.z; a0.w += v0.w;
        a1.x += v1.x; a1.y += v1.y; a1.z += v1.z; a1.w += v1.w;
        a0.x += v2.x; a0.y += v2.y; a0.z += v2.z; a0.w += v2.w;
        a1.x += v3.x; a1.y += v3.y; a1.z += v3.z; a1.w += v3.w;
    }
    for (; j < end; j++) {
        int n0 = __ldg(g_hlist + j);
        float4 v0 = __ldg(reinterpret_cast<const float4*>(g_y2 + (size_t)n0 * D2C) + lane);
        a0.x += v0.x; a0.y += v0.y; a0.z += v0.z; a0.w += v0.w;
    }
    float bi = g_binv[g];
    float4 r;
    r.x = (a0.x + a1.x) * bi;
    r.y = (a0.y + a1.y) * bi;
    r.z = (a0.z + a1.z) * bi;
    r.w = (a0.w + a1.w) * bi;
    reinterpret_cast<float4*>(g_e2 + (size_t)g * D2C)[lane] = r;
}

// out[n] = relu(dinv[n] * sum over member hedges of e2[h] + b2)  (fused epilogue)
__global__ void __launch_bounds__(256) h2n2_k(const float* __restrict__ b2,
                                              float* __restrict__ out) {
    int g = blockIdx.x * 16 + (threadIdx.x >> 4);
    if (g >= N_NODESC) return;
    int lane = threadIdx.x & 15;
    int base = g_noff[g], end = g_noff[g + 1];
    float4 a0 = make_float4(0.f, 0.f, 0.f, 0.f);
    float4 a1 = make_float4(0.f, 0.f, 0.f, 0.f);
    int j = base;
    for (; j + 4 <= end; j += 4) {
        int h0 = __ldg(g_nlist + j + 0);
        int h1 = __ldg(g_nlist + j + 1);
        int h2 = __ldg(g_nlist + j + 2);
        int h3 = __ldg(g_nlist + j + 3);
        float4 v0 = __ldg(reinterpret_cast<const float4*>(g_e2 + (size_t)h0 * D2C) + lane);
        float4 v1 = __ldg(reinterpret_cast<const float4*>(g_e2 + (size_t)h1 * D2C) + lane);
        float4 v2 = __ldg(reinterpret_cast<const float4*>(g_e2 + (size_t)h2 * D2C) + lane);
        float4 v3 = __ldg(reinterpret_cast<const float4*>(g_e2 + (size_t)h3 * D2C) + lane);
        a0.x += v0.x; a0.y += v0.y; a0.z += v0.z; a0.w += v0.w;
        a1.x += v1.x; a1.y += v1.y; a1.z += v1.z; a1.w += v1.w;
        a0.x += v2.x; a0.y += v2.y; a0.z += v2.z; a0.w += v2.w;
        a1.x += v3.x; a1.y += v3.y; a1.z += v3.z; a1.w += v3.w;
    }
    for (; j < end; j++) {
        int h0 = __ldg(g_nlist + j);
        float4 v0 = __ldg(reinterpret_cast<const float4*>(g_e2 + (size_t)h0 * D2C) + lane);
        a0.x += v0.x; a0.y += v0.y; a0.z += v0.z; a0.w += v0.w;
    }
    float di = g_dinv[g];
    float4 b = __ldg(reinterpret_cast<const float4*>(b2) + lane);
    float4 r;
    r.x = fmaxf(fmaf(a0.x + a1.x, di, b.x), 0.f);
    r.y = fmaxf(fmaf(a0.y + a1.y, di, b.y), 0.f);
    r.z = fmaxf(fmaf(a0.z + a1.z, di, b.z), 0.f);
    r.w = fmaxf(fmaf(a0.w + a1.w, di, b.w), 0.f);
    reinterpret_cast<float4*>(out + (size_t)g * D2C)[lane] = r;
}

// ---------------------------------------------------------------------------
// tf32 tensor-core GEMM: C = A @ B (+bias, relu). fp32 in, tf32 mma, fp32 acc.
// BM x BN tile, BK=32 k-tile, 8 warps (WARPS_M x WARPS_N).
// ---------------------------------------------------------------------------
__device__ __forceinline__ uint32_t f2tf32(float f) {
    uint32_t u;
    asm("cvt.rna.tf32.f32 %0, %1;" : "=r"(u) : "f"(f));
    return u;
}

__device__ __forceinline__ void mma_tf32(float& d0, float& d1, float& d2, float& d3,
                                         uint32_t a0, uint32_t a1, uint32_t a2, uint32_t a3,
                                         uint32_t b0, uint32_t b1) {
    asm volatile(
        "mma.sync.aligned.m16n8k8.row.col.f32.tf32.tf32.f32 "
        "{%0,%1,%2,%3}, {%4,%5,%6,%7}, {%8,%9}, {%0,%1,%2,%3};"
        : "+f"(d0), "+f"(d1), "+f"(d2), "+f"(d3)
        : "r"(a0), "r"(a1), "r"(a2), "r"(a3), "r"(b0), "r"(b1));
}

template <int BM, int BN, int BK, int WARPS_M, int WARPS_N, bool EPI>
__device__ __forceinline__ void gemm_tf32_body(const float* __restrict__ A,
                                               const float* __restrict__ B,
                                               const float* __restrict__ bias,
                                               float* __restrict__ C,
                                               int M, int N, int K) {
    constexpr int THREADS = WARPS_M * WARPS_N * 32;
    constexpr int WM = BM / WARPS_M;       // warp tile M
    constexpr int WN = BN / WARPS_N;       // warp tile N
    constexpr int MI = WM / 16;            // m16 tiles per warp
    constexpr int NI = WN / 8;             // n8 tiles per warp
    constexpr int AV = (BM * BK / 4) / THREADS;
    constexpr int BV = (BK * BN / 4) / THREADS;

    __shared__ __align__(16) uint32_t As[BK][BM + 4];  // [k][m], tf32
    __shared__ __align__(16) uint32_t Bs[BK][BN + 4];  // [k][n], tf32

    const int tid  = threadIdx.x;
    const int warp = tid >> 5;
    const int lane = tid & 31;
    const int wm   = warp / WARPS_N;
    const int wn   = warp % WARPS_N;
    const int row0 = blockIdx.y * BM;
    const int col0 = blockIdx.x * BN;

    float acc[MI][NI][4];
#pragma unroll
    for (int i = 0; i < MI; i++)
#pragma unroll
        for (int j = 0; j < NI; j++)
#pragma unroll
            for (int c = 0; c < 4; c++) acc[i][j][c] = 0.f;

    const int lq = lane >> 2;   // lane/4  (group id)
    const int lr = lane & 3;    // lane%4  (thread in group)

    for (int kt = 0; kt < K; kt += BK) {
        // Load+convert A tile (BM x BK) -> As[k][m]
#pragma unroll
        for (int i = 0; i < AV; i++) {
            int idx = tid + i * THREADS;
            int r   = idx / (BK / 4);
            int kc  = (idx % (BK / 4)) * 4;
            int grow = row0 + r;
            float4 v = make_float4(0.f, 0.f, 0.f, 0.f);
            if (grow < M)
                v = __ldg(reinterpret_cast<const float4*>(&A[(size_t)grow * K + kt + kc]));
            As[kc + 0][r] = f2tf32(v.x);
            As[kc + 1][r] = f2tf32(v.y);
            As[kc + 2][r] = f2tf32(v.z);
            As[kc + 3][r] = f2tf32(v.w);
        }
        // Load+convert B tile (BK x BN) -> Bs[k][n]
#pragma unroll
        for (int i = 0; i < BV; i++) {
            int idx = tid + i * THREADS;
            int r   = idx / (BN / 4);
            int c   = (idx % (BN / 4)) * 4;
            float4 v = __ldg(reinterpret_cast<const float4*>(&B[(size_t)(kt + r) * N + col0 + c]));
            uint4 u;
            u.x = f2tf32(v.x); u.y = f2tf32(v.y); u.z = f2tf32(v.z); u.w = f2tf32(v.w);
            *reinterpret_cast<uint4*>(&Bs[r][c]) = u;
        }
        __syncthreads();

#pragma unroll
        for (int ks = 0; ks < BK; ks += 8) {
            uint32_t af[MI][4];
            uint32_t bf[NI][2];
            // PTX m16n8k8 A fragment:
            //   a0 = A[lq][lr]      a1 = A[lq+8][lr]
            //   a2 = A[lq][lr+4]    a3 = A[lq+8][lr+4]
#pragma unroll
            for (int i = 0; i < MI; i++) {
                int m0 = wm * WM + i * 16;
                af[i][0] = As[ks + lr    ][m0 + lq];
                af[i][1] = As[ks + lr    ][m0 + lq + 8];
                af[i][2] = As[ks + lr + 4][m0 + lq];
                af[i][3] = As[ks + lr + 4][m0 + lq + 8];
            }
            // B fragment: b0 = B[lr][lq], b1 = B[lr+4][lq]
#pragma unroll
            for (int j = 0; j < NI; j++) {
                int n0 = wn * WN + j * 8;
                bf[j][0] = Bs[ks + lr    ][n0 + lq];
                bf[j][1] = Bs[ks + lr + 4][n0 + lq];
            }
#pragma unroll
            for (int i = 0; i < MI; i++)
#pragma unroll
                for (int j = 0; j < NI; j++)
                    mma_tf32(acc[i][j][0], acc[i][j][1], acc[i][j][2], acc[i][j][3],
                             af[i][0], af[i][1], af[i][2], af[i][3],
                             bf[j][0], bf[j][1]);
        }
        __syncthreads();
    }

    // Epilogue: c0,c1 at (row, col..col+1); c2,c3 at (row+8, col..col+1)
#pragma unroll
    for (int i = 0; i < MI; i++) {
#pragma unroll
        for (int j = 0; j < NI; j++) {
            int row = row0 + wm * WM + i * 16 + lq;
            int col = col0 + wn * WN + j * 8 + 2 * lr;
            float2 v0 = make_float2(acc[i][j][0], acc[i][j][1]);
            float2 v1 = make_float2(acc[i][j][2], acc[i][j][3]);
            if (EPI) {
                float b0 = bias[col], b1 = bias[col + 1];
                v0.x = fmaxf(v0.x + b0, 0.f);
                v0.y = fmaxf(v0.y + b1, 0.f);
                v1.x = fmaxf(v1.x + b0, 0.f);
                v1.y = fmaxf(v1.y + b1, 0.f);
            }
            if (row < M)
                *reinterpret_cast<float2*>(&C[(size_t)row * N + col]) = v0;
            if (row + 8 < M)
                *reinterpret_cast<float2*>(&C[(size_t)(row + 8) * N + col]) = v1;
        }
    }
}

// GEMM1: g_h = relu(g_agg1 @ W1 + b1)   [50000x128]@[128x256]
__global__ void __launch_bounds__(256) gemm1_k(const float* __restrict__ W1,
                                               const float* __restrict__ b1) {
    gemm_tf32_body<128, 128, 32, 2, 4, true>(g_agg1, W1, b1, g_h, N_NODESC, D1C, IN_C);
}

// GEMM2: g_y2 = g_h @ W2   [50000x256]@[256x64]
__global__ void __launch_bounds__(256) gemm2_k(const float* __restrict__ W2) {
    gemm_tf32_body<128, 64, 32, 4, 2, false>(g_h, W2, nullptr, g_y2, N_NODESC, D2C, D1C);
}

// ---------------------------------------------------------------------------
// Launch
// ---------------------------------------------------------------------------
extern "C" void kernel_launch(void* const* d_in, const int* in_sizes, int n_in,
                              void* d_out, int out_size) {
    const float* x    = (const float*)d_in[0];
    const int*   edge = (const int*)d_in[1];
    const float* W1   = (const float*)d_in[2];
    const float* b1   = (const float*)d_in[3];
    const float* W2   = (const float*)d_in[4];
    const float* b2   = (const float*)d_in[5];
    float*       out  = (float*)d_out;

    const int* ni = edge;          // edge[0] = node_idx
    const int* hi = edge + NNZC;   // edge[1] = hedge_idx

    // CSR construction
    zero_k<<<256, 256>>>();
    hist_k<<<(NNZC / 2 + 255) / 256, 256>>>(ni, hi);
    psum_k<<<NBLK, 256>>>();
    pscan_k<<<1, 256>>>();
    fill_k<<<NBLK, 256>>>();
    build_k<<<(NNZC / 2 + 255) / 256, 256>>>(ni, hi);

    // Layer 1 aggregation at 128 channels (gather, no atomics)
    n2h1_k<<<(N_HEDGESC + 7) / 8, 256>>>(x);
    h2n1_k<<<(N_NODESC + 7) / 8, 256>>>();

    // h = relu(agg1 @ W1 + b1) ; y2 = h @ W2   (tf32 tensor cores)
    {
        dim3 g1(D1C / 128, (N_NODESC + 127) / 128);
        gemm1_k<<<g1, 256>>>(W1, b1);
        dim3 g2(D2C / 64, (N_NODESC + 127) / 128);
        gemm2_k<<<g2, 256>>>(W2);
    }

    // Layer 2 aggregation at 64 channels (gather) + fused final epilogue
    n2h2_k<<<(N_HEDGESC + 15) / 16, 256>>>();
    h2n2_k<<<(N_NODESC + 15) / 16, 256>>>(b2, out);
}

// round 7
// speedup vs baseline: 2.2524x; 1.3460x over previous
#include <cuda_runtime.h>
#include <cuda_fp16.h>
#include <cstdint>
#include <cstddef>

// Problem constants (fixed shapes for Hgnn_17394617548829)
#define N_NODESC 50000
#define N_HEDGESC 5000
#define NNZC 800000
#define IN_C 128
#define D1C 256
#define D2C 64

// Scan chunking: 256 elements per block
#define NBLK_H 20    // ceil(5000/256)
#define NBLK_N 196   // ceil(50000/256)
#define NBLK   216

// ---------------------------------------------------------------------------
// Scratch (static device globals; no allocation anywhere)
// ---------------------------------------------------------------------------
__device__ __half g_xh  [(size_t)N_NODESC * IN_C];   // 12.8 MB (x in fp16)
__device__ __half g_e1h [(size_t)N_HEDGESC * IN_C];  // 1.28 MB
__device__ __half g_a1h [(size_t)N_NODESC * IN_C];   // 12.8 MB (agg1 fp16)
__device__ __half g_hh  [(size_t)N_NODESC * D1C];    // 25.6 MB
__device__ __half g_y2h [(size_t)N_NODESC * D2C];    // 6.4 MB
__device__ __half g_e2h [(size_t)N_HEDGESC * D2C];   // 0.64 MB
__device__ __half g_w1h [(size_t)D1C * IN_C];        // W1^T [N=256][K=128]
__device__ __half g_w2h [(size_t)D2C * D1C];         // W2^T [N=64][K=256]
__device__ int   g_cnt [N_HEDGESC];
__device__ int   g_deg [N_NODESC];
__device__ int   g_hoff[N_HEDGESC + 1];
__device__ int   g_noff[N_NODESC + 1];
__device__ int   g_hcur[N_HEDGESC];
__device__ int   g_ncur[N_NODESC];
__device__ int   g_hlist[NNZC];
__device__ int   g_nlist[NNZC];
__device__ float g_dinv[N_NODESC];
__device__ float g_binv[N_HEDGESC];
__device__ int   g_part[NBLK];
__device__ int   g_partoff[NBLK];

// ---------------------------------------------------------------------------
// fp16 helpers
// ---------------------------------------------------------------------------
__device__ __forceinline__ void acc_h2(float4& a, uint2 u) {
    __half2 p0 = *reinterpret_cast<__half2*>(&u.x);
    __half2 p1 = *reinterpret_cast<__half2*>(&u.y);
    float2 f0 = __half22float2(p0);
    float2 f1 = __half22float2(p1);
    a.x += f0.x; a.y += f0.y; a.z += f1.x; a.w += f1.y;
}

__device__ __forceinline__ uint2 pack_h2(float x, float y, float z, float w) {
    __half2 h0 = __floats2half2_rn(x, y);
    __half2 h1 = __floats2half2_rn(z, w);
    uint2 u;
    u.x = *reinterpret_cast<unsigned*>(&h0);
    u.y = *reinterpret_cast<unsigned*>(&h1);
    return u;
}

// ---------------------------------------------------------------------------
// 0. fp16 conversions: x -> xh, W1 -> w1h (transposed), W2 -> w2h (transposed)
// ---------------------------------------------------------------------------
__global__ void __launch_bounds__(256) cvt_k(const float* __restrict__ x,
                                             const float* __restrict__ W1,
                                             const float* __restrict__ W2) {
    int i = blockIdx.x * blockDim.x + threadIdx.x;
    int stride = gridDim.x * blockDim.x;
    const float4* x4 = reinterpret_cast<const float4*>(x);
    uint2* xh2 = reinterpret_cast<uint2*>(g_xh);
    for (int j = i; j < N_NODESC * IN_C / 4; j += stride) {
        float4 v = x4[j];
        xh2[j] = pack_h2(v.x, v.y, v.z, v.w);
    }
    for (int j = i; j < D1C * IN_C; j += stride) {
        int n = j / IN_C, k = j % IN_C;
        g_w1h[j] = __float2half(W1[(size_t)k * D1C + n]);
    }
    for (int j = i; j < D2C * D1C; j += stride) {
        int n = j / D1C, k = j % D1C;
        g_w2h[j] = __float2half(W2[(size_t)k * D2C + n]);
    }
}

// ---------------------------------------------------------------------------
// 1. zero degree counters
// ---------------------------------------------------------------------------
__global__ void zero_k() {
    int i = blockIdx.x * blockDim.x + threadIdx.x;
    int stride = gridDim.x * blockDim.x;
    for (int j = i; j < N_NODESC; j += stride) g_deg[j] = 0;
    for (int j = i; j < N_HEDGESC; j += stride) g_cnt[j] = 0;
}

// ---------------------------------------------------------------------------
// 2. degree histograms (2 edges per thread)
// ---------------------------------------------------------------------------
__global__ void __launch_bounds__(256) hist_k(const int* __restrict__ ni,
                                              const int* __restrict__ hi) {
    int i = blockIdx.x * blockDim.x + threadIdx.x;
    if (2 * i >= NNZC) return;
    int2 nn = *reinterpret_cast<const int2*>(ni + 2 * i);
    int2 hh = *reinterpret_cast<const int2*>(hi + 2 * i);
    atomicAdd(&g_deg[nn.x], 1);
    atomicAdd(&g_deg[nn.y], 1);
    atomicAdd(&g_cnt[hh.x], 1);
    atomicAdd(&g_cnt[hh.y], 1);
}

// ---------------------------------------------------------------------------
// 3a/3b/3c. segmented exclusive scan (per-chunk sums, chunk scan, fill)
// ---------------------------------------------------------------------------
__global__ void __launch_bounds__(256) psum_k() {
    __shared__ int sh[256];
    int b = blockIdx.x;
    const int* src;
    int idx, n;
    if (b < NBLK_H) { src = g_cnt; idx = b * 256 + threadIdx.x; n = N_HEDGESC; }
    else            { src = g_deg; idx = (b - NBLK_H) * 256 + threadIdx.x; n = N_NODESC; }
    int v = (idx < n) ? src[idx] : 0;
    sh[threadIdx.x] = v;
    __syncthreads();
    for (int d = 128; d > 0; d >>= 1) {
        if (threadIdx.x < d) sh[threadIdx.x] += sh[threadIdx.x + d];
        __syncthreads();
    }
    if (threadIdx.x == 0) g_part[b] = sh[0];
}

__global__ void __launch_bounds__(256) pscan_k() {
    __shared__ int sh[NBLK];
    int tid = threadIdx.x;
    if (tid < NBLK) sh[tid] = g_part[tid];
    __syncthreads();
    if (tid == 0) {
        int run = 0;
        for (int i = 0; i < NBLK_H; i++) { int c = sh[i]; sh[i] = run; run += c; }
        run = 0;
        for (int i = NBLK_H; i < NBLK; i++) { int c = sh[i]; sh[i] = run; run += c; }
    }
    __syncthreads();
    if (tid < NBLK) g_partoff[tid] = sh[tid];
}

__global__ void __launch_bounds__(256) fill_k() {
    __shared__ int sh[256];
    int b = blockIdx.x;
    int tid = threadIdx.x;
    const int* src; int* off; int* cur; float* inv;
    int idx, n;
    if (b < NBLK_H) {
        src = g_cnt; off = g_hoff; cur = g_hcur; inv = g_binv;
        idx = b * 256 + tid; n = N_HEDGESC;
    } else {
        src = g_deg; off = g_noff; cur = g_ncur; inv = g_dinv;
        idx = (b - NBLK_H) * 256 + tid; n = N_NODESC;
    }
    int v = (idx < n) ? src[idx] : 0;
    sh[tid] = v;
    __syncthreads();
    for (int d = 1; d < 256; d <<= 1) {
        int t = (tid >= d) ? sh[tid - d] : 0;
        __syncthreads();
        sh[tid] += t;
        __syncthreads();
    }
    if (idx < n) {
        int excl = sh[tid] - v + g_partoff[b];
        off[idx] = excl;
        cur[idx] = excl;
        inv[idx] = (v > 0) ? 1.0f / (float)v : 0.0f;
    }
    if (b == 0 && tid == 0) {
        g_hoff[N_HEDGESC] = NNZC;
        g_noff[N_NODESC]  = NNZC;
    }
}

// ---------------------------------------------------------------------------
// 4. scatter edges into both CSR member lists
// ---------------------------------------------------------------------------
__global__ void __launch_bounds__(256) build_k(const int* __restrict__ ni,
                                               const int* __restrict__ hi) {
    int i = blockIdx.x * blockDim.x + threadIdx.x;
    if (2 * i >= NNZC) return;
    int2 nn = *reinterpret_cast<const int2*>(ni + 2 * i);
    int2 hh = *reinterpret_cast<const int2*>(hi + 2 * i);
    int p0 = atomicAdd(&g_hcur[hh.x], 1);
    int p1 = atomicAdd(&g_hcur[hh.y], 1);
    int q0 = atomicAdd(&g_ncur[nn.x], 1);
    int q1 = atomicAdd(&g_ncur[nn.y], 1);
    g_hlist[p0] = nn.x;
    g_hlist[p1] = nn.y;
    g_nlist[q0] = hh.x;
    g_nlist[q1] = hh.y;
}

// ---------------------------------------------------------------------------
// Gather kernels, fp16 payloads, fp32 accumulation.
// 128 ch: warp per segment, uint2 (4 halves) per lane.
// 64 ch:  16-lane group per segment.
// ---------------------------------------------------------------------------
// e1h[h] = binv[h] * sum x_h[n]
__global__ void __launch_bounds__(256) n2h1_k() {
    int w = blockIdx.x * 8 + (threadIdx.x >> 5);
    if (w >= N_HEDGESC) return;
    int lane = threadIdx.x & 31;
    int base = g_hoff[w], end = g_hoff[w + 1];
    float4 a0 = make_float4(0.f, 0.f, 0.f, 0.f);
    float4 a1 = make_float4(0.f, 0.f, 0.f, 0.f);
    int j = base;
    for (; j + 4 <= end; j += 4) {
        int n0 = __ldg(g_hlist + j + 0);
        int n1 = __ldg(g_hlist + j + 1);
        int n2 = __ldg(g_hlist + j + 2);
        int n3 = __ldg(g_hlist + j + 3);
        uint2 u0 = __ldg(reinterpret_cast<const uint2*>(g_xh + (size_t)n0 * IN_C) + lane);
        uint2 u1 = __ldg(reinterpret_cast<const uint2*>(g_xh + (size_t)n1 * IN_C) + lane);
        uint2 u2 = __ldg(reinterpret_cast<const uint2*>(g_xh + (size_t)n2 * IN_C) + lane);
        uint2 u3 = __ldg(reinterpret_cast<const uint2*>(g_xh + (size_t)n3 * IN_C) + lane);
        acc_h2(a0, u0); acc_h2(a1, u1); acc_h2(a0, u2); acc_h2(a1, u3);
    }
    for (; j < end; j++) {
        int n0 = __ldg(g_hlist + j);
        uint2 u0 = __ldg(reinterpret_cast<const uint2*>(g_xh + (size_t)n0 * IN_C) + lane);
        acc_h2(a0, u0);
    }
    float bi = g_binv[w];
    reinterpret_cast<uint2*>(g_e1h + (size_t)w * IN_C)[lane] =
        pack_h2((a0.x + a1.x) * bi, (a0.y + a1.y) * bi,
                (a0.z + a1.z) * bi, (a0.w + a1.w) * bi);
}

// a1h[n] = dinv[n] * sum e1h[h]
__global__ void __launch_bounds__(256) h2n1_k() {
    int w = blockIdx.x * 8 + (threadIdx.x >> 5);
    if (w >= N_NODESC) return;
    int lane = threadIdx.x & 31;
    int base = g_noff[w], end = g_noff[w + 1];
    float4 a0 = make_float4(0.f, 0.f, 0.f, 0.f);
    float4 a1 = make_float4(0.f, 0.f, 0.f, 0.f);
    int j = base;
    for (; j + 4 <= end; j += 4) {
        int h0 = __ldg(g_nlist + j + 0);
        int h1 = __ldg(g_nlist + j + 1);
        int h2 = __ldg(g_nlist + j + 2);
        int h3 = __ldg(g_nlist + j + 3);
        uint2 u0 = __ldg(reinterpret_cast<const uint2*>(g_e1h + (size_t)h0 * IN_C) + lane);
        uint2 u1 = __ldg(reinterpret_cast<const uint2*>(g_e1h + (size_t)h1 * IN_C) + lane);
        uint2 u2 = __ldg(reinterpret_cast<const uint2*>(g_e1h + (size_t)h2 * IN_C) + lane);
        uint2 u3 = __ldg(reinterpret_cast<const uint2*>(g_e1h + (size_t)h3 * IN_C) + lane);
        acc_h2(a0, u0); acc_h2(a1, u1); acc_h2(a0, u2); acc_h2(a1, u3);
    }
    for (; j < end; j++) {
        int h0 = __ldg(g_nlist + j);
        uint2 u0 = __ldg(reinterpret_cast<const uint2*>(g_e1h + (size_t)h0 * IN_C) + lane);
        acc_h2(a0, u0);
    }
    float di = g_dinv[w];
    reinterpret_cast<uint2*>(g_a1h + (size_t)w * IN_C)[lane] =
        pack_h2((a0.x + a1.x) * di, (a0.y + a1.y) * di,
                (a0.z + a1.z) * di, (a0.w + a1.w) * di);
}

// e2h[h] = binv[h] * sum y2h[n]   (64 ch)
__global__ void __launch_bounds__(256) n2h2_k() {
    int g = blockIdx.x * 16 + (threadIdx.x >> 4);
    if (g >= N_HEDGESC) return;
    int lane = threadIdx.x & 15;
    int base = g_hoff[g], end = g_hoff[g + 1];
    float4 a0 = make_float4(0.f, 0.f, 0.f, 0.f);
    float4 a1 = make_float4(0.f, 0.f, 0.f, 0.f);
    int j = base;
    for (; j + 4 <= end; j += 4) {
        int n0 = __ldg(g_hlist + j + 0);
        int n1 = __ldg(g_hlist + j + 1);
        int n2 = __ldg(g_hlist + j + 2);
        int n3 = __ldg(g_hlist + j + 3);
        uint2 u0 = __ldg(reinterpret_cast<const uint2*>(g_y2h + (size_t)n0 * D2C) + lane);
        uint2 u1 = __ldg(reinterpret_cast<const uint2*>(g_y2h + (size_t)n1 * D2C) + lane);
        uint2 u2 = __ldg(reinterpret_cast<const uint2*>(g_y2h + (size_t)n2 * D2C) + lane);
        uint2 u3 = __ldg(reinterpret_cast<const uint2*>(g_y2h + (size_t)n3 * D2C) + lane);
        acc_h2(a0, u0); acc_h2(a1, u1); acc_h2(a0, u2); acc_h2(a1, u3);
    }
    for (; j < end; j++) {
        int n0 = __ldg(g_hlist + j);
        uint2 u0 = __ldg(reinterpret_cast<const uint2*>(g_y2h + (size_t)n0 * D2C) + lane);
        acc_h2(a0, u0);
    }
    float bi = g_binv[g];
    reinterpret_cast<uint2*>(g_e2h + (size_t)g * D2C)[lane] =
        pack_h2((a0.x + a1.x) * bi, (a0.y + a1.y) * bi,
                (a0.z + a1.z) * bi, (a0.w + a1.w) * bi);
}

// out[n] = relu(dinv[n] * sum e2h[h] + b2)   (fp32 output, fused epilogue)
__global__ void __launch_bounds__(256) h2n2_k(const float* __restrict__ b2,
                                              float* __restrict__ out) {
    int g = blockIdx.x * 16 + (threadIdx.x >> 4);
    if (g >= N_NODESC) return;
    int lane = threadIdx.x & 15;
    int base = g_noff[g], end = g_noff[g + 1];
    float4 a0 = make_float4(0.f, 0.f, 0.f, 0.f);
    float4 a1 = make_float4(0.f, 0.f, 0.f, 0.f);
    int j = base;
    for (; j + 4 <= end; j += 4) {
        int h0 = __ldg(g_nlist + j + 0);
        int h1 = __ldg(g_nlist + j + 1);
        int h2 = __ldg(g_nlist + j + 2);
        int h3 = __ldg(g_nlist + j + 3);
        uint2 u0 = __ldg(reinterpret_cast<const uint2*>(g_e2h + (size_t)h0 * D2C) + lane);
        uint2 u1 = __ldg(reinterpret_cast<const uint2*>(g_e2h + (size_t)h1 * D2C) + lane);
        uint2 u2 = __ldg(reinterpret_cast<const uint2*>(g_e2h + (size_t)h2 * D2C) + lane);
        uint2 u3 = __ldg(reinterpret_cast<const uint2*>(g_e2h + (size_t)h3 * D2C) + lane);
        acc_h2(a0, u0); acc_h2(a1, u1); acc_h2(a0, u2); acc_h2(a1, u3);
    }
    for (; j < end; j++) {
        int h0 = __ldg(g_nlist + j);
        uint2 u0 = __ldg(reinterpret_cast<const uint2*>(g_e2h + (size_t)h0 * D2C) + lane);
        acc_h2(a0, u0);
    }
    float di = g_dinv[g];
    float4 b = __ldg(reinterpret_cast<const float4*>(b2) + lane);
    float4 r;
    r.x = fmaxf(fmaf(a0.x + a1.x, di, b.x), 0.f);
    r.y = fmaxf(fmaf(a0.y + a1.y, di, b.y), 0.f);
    r.z = fmaxf(fmaf(a0.z + a1.z, di, b.z), 0.f);
    r.w = fmaxf(fmaf(a0.w + a1.w, di, b.w), 0.f);
    reinterpret_cast<float4*>(out + (size_t)g * D2C)[lane] = r;
}

// ---------------------------------------------------------------------------
// fp16 tensor-core GEMM: C_h = A_h @ B_h^T (+fp32 bias, relu).
// A: [M][K] halves row-major. Bt: [N][K] halves (pre-transposed weights).
// mma.m16n8k16.f32.f16.f16.f32, fp32 accumulate, fp16 output.
// ---------------------------------------------------------------------------
__device__ __forceinline__ void mma_f16(float& d0, float& d1, float& d2, float& d3,
                                        uint32_t a0, uint32_t a1, uint32_t a2, uint32_t a3,
                                        uint32_t b0, uint32_t b1) {
    asm volatile(
        "mma.sync.aligned.m16n8k16.row.col.f32.f16.f16.f32 "
        "{%0,%1,%2,%3}, {%4,%5,%6,%7}, {%8,%9}, {%0,%1,%2,%3};"
        : "+f"(d0), "+f"(d1), "+f"(d2), "+f"(d3)
        : "r"(a0), "r"(a1), "r"(a2), "r"(a3), "r"(b0), "r"(b1));
}

template <int BM, int BN, int BK, int WARPS_M, int WARPS_N, bool EPI>
__device__ __forceinline__ void gemm_f16_body(const __half* __restrict__ A,
                                              const __half* __restrict__ Bt,
                                              const float* __restrict__ bias,
                                              __half* __restrict__ C,
                                              int M, int N, int K) {
    constexpr int THREADS = WARPS_M * WARPS_N * 32;
    constexpr int WM = BM / WARPS_M;
    constexpr int WN = BN / WARPS_N;
    constexpr int MI = WM / 16;
    constexpr int NI = WN / 8;
    constexpr int PAD = 8;                         // halves; keeps 16B alignment
    constexpr int AV = (BM * BK / 8) / THREADS;    // uint4 copies per thread
    constexpr int BV = (BN * BK / 8) / THREADS;

    __shared__ __align__(16) __half As[BM][BK + PAD];
    __shared__ __align__(16) __half Bs[BN][BK + PAD];

    const int tid  = threadIdx.x;
    const int warp = tid >> 5;
    const int lane = tid & 31;
    const int wm   = warp / WARPS_N;
    const int wn   = warp % WARPS_N;
    const int row0 = blockIdx.y * BM;
    const int col0 = blockIdx.x * BN;
    const int lq   = lane >> 2;
    const int lr   = lane & 3;

    float acc[MI][NI][4];
#pragma unroll
    for (int i = 0; i < MI; i++)
#pragma unroll
        for (int j = 0; j < NI; j++)
#pragma unroll
            for (int c = 0; c < 4; c++) acc[i][j][c] = 0.f;

    for (int kt = 0; kt < K; kt += BK) {
        // A tile: BM x BK halves, uint4 (8 halves) per copy
#pragma unroll
        for (int i = 0; i < AV; i++) {
            int idx = tid + i * THREADS;
            int m   = idx / (BK / 8);
            int kc  = (idx % (BK / 8)) * 8;
            int grow = row0 + m;
            uint4 v = make_uint4(0, 0, 0, 0);
            if (grow < M)
                v = __ldg(reinterpret_cast<const uint4*>(A + (size_t)grow * K + kt + kc));
            *reinterpret_cast<uint4*>(&As[m][kc]) = v;
        }
        // B tile: BN x BK halves from pre-transposed [N][K]
#pragma unroll
        for (int i = 0; i < BV; i++) {
            int idx = tid + i * THREADS;
            int n   = idx / (BK / 8);
            int kc  = (idx % (BK / 8)) * 8;
            uint4 v = __ldg(reinterpret_cast<const uint4*>(Bt + (size_t)(col0 + n) * K + kt + kc));
            *reinterpret_cast<uint4*>(&Bs[n][kc]) = v;
        }
        __syncthreads();

#pragma unroll
        for (int ks = 0; ks < BK; ks += 16) {
            uint32_t af[MI][4];
            uint32_t bf[NI][2];
            // m16n8k16 A fragment: a0=(lq, 2lr..2lr+1), a1=(lq+8, same),
            //                      a2=(lq, +8),          a3=(lq+8, +8)
#pragma unroll
            for (int i = 0; i < MI; i++) {
                int m0 = wm * WM + i * 16;
                af[i][0] = *reinterpret_cast<const uint32_t*>(&As[m0 + lq    ][ks + 2 * lr    ]);
                af[i][1] = *reinterpret_cast<const uint32_t*>(&As[m0 + lq + 8][ks + 2 * lr    ]);
                af[i][2] = *reinterpret_cast<const uint32_t*>(&As[m0 + lq    ][ks + 2 * lr + 8]);
                af[i][3] = *reinterpret_cast<const uint32_t*>(&As[m0 + lq + 8][ks + 2 * lr + 8]);
            }
            // B fragment: b0=(k=2lr..2lr+1, n=lq), b1=(k+8, n=lq)
#pragma unroll
            for (int j = 0; j < NI; j++) {
                int n0 = wn * WN + j * 8;
                bf[j][0] = *reinterpret_cast<const uint32_t*>(&Bs[n0 + lq][ks + 2 * lr    ]);
                bf[j][1] = *reinterpret_cast<const uint32_t*>(&Bs[n0 + lq][ks + 2 * lr + 8]);
            }
#pragma unroll
            for (int i = 0; i < MI; i++)
#pragma unroll
                for (int j = 0; j < NI; j++)
                    mma_f16(acc[i][j][0], acc[i][j][1], acc[i][j][2], acc[i][j][3],
                            af[i][0], af[i][1], af[i][2], af[i][3],
                            bf[j][0], bf[j][1]);
        }
        __syncthreads();
    }

    // Epilogue: (c0,c1)@(row,col..col+1), (c2,c3)@(row+8, same). half2 stores.
#pragma unroll
    for (int i = 0; i < MI; i++) {
#pragma unroll
        for (int j = 0; j < NI; j++) {
            int row = row0 + wm * WM + i * 16 + lq;
            int col = col0 + wn * WN + j * 8 + 2 * lr;
            float2 v0 = make_float2(acc[i][j][0], acc[i][j][1]);
            float2 v1 = make_float2(acc[i][j][2], acc[i][j][3]);
            if (EPI) {
                float b0 = bias[col], b1 = bias[col + 1];
                v0.x = fmaxf(v0.x + b0, 0.f);
                v0.y = fmaxf(v0.y + b1, 0.f);
                v1.x = fmaxf(v1.x + b0, 0.f);
                v1.y = fmaxf(v1.y + b1, 0.f);
            }
            if (row < M)
                *reinterpret_cast<__half2*>(&C[(size_t)row * N + col]) =
                    __floats2half2_rn(v0.x, v0.y);
            if (row + 8 < M)
                *reinterpret_cast<__half2*>(&C[(size_t)(row + 8) * N + col]) =
                    __floats2half2_rn(v1.x, v1.y);
        }
    }
}

// GEMM1: g_hh = relu(g_a1h @ W1 + b1)   [50000x128]@[128x256]
__global__ void __launch_bounds__(256) gemm1_k(const float* __restrict__ b1) {
    gemm_f16_body<128, 128, 32, 2, 4, true>(g_a1h, g_w1h, b1, g_hh, N_NODESC, D1C, IN_C);
}

// GEMM2: g_y2h = g_hh @ W2   [50000x256]@[256x64]
__global__ void __launch_bounds__(256) gemm2_k() {
    gemm_f16_body<128, 64, 32, 4, 2, false>(g_hh, g_w2h, nullptr, g_y2h, N_NODESC, D2C, D1C);
}

// ---------------------------------------------------------------------------
// Launch
// ---------------------------------------------------------------------------
extern "C" void kernel_launch(void* const* d_in, const int* in_sizes, int n_in,
                              void* d_out, int out_size) {
    const float* x    = (const float*)d_in[0];
    const int*   edge = (const int*)d_in[1];
    const float* W1   = (const float*)d_in[2];
    const float* b1   = (const float*)d_in[3];
    const float* W2   = (const float*)d_in[4];
    const float* b2   = (const float*)d_in[5];
    float*       out  = (float*)d_out;

    const int* ni = edge;          // edge[0] = node_idx
    const int* hi = edge + NNZC;   // edge[1] = hedge_idx

    // fp16 conversions + CSR construction
    cvt_k<<<1024, 256>>>(x, W1, W2);
    zero_k<<<256, 256>>>();
    hist_k<<<(NNZC / 2 + 255) / 256, 256>>>(ni, hi);
    psum_k<<<NBLK, 256>>>();
    pscan_k<<<1, 256>>>();
    fill_k<<<NBLK, 256>>>();
    build_k<<<(NNZC / 2 + 255) / 256, 256>>>(ni, hi);

    // Layer 1 aggregation at 128 channels (fp16 gather)
    n2h1_k<<<(N_HEDGESC + 7) / 8, 256>>>();
    h2n1_k<<<(N_NODESC + 7) / 8, 256>>>();

    // h = relu(agg1 @ W1 + b1) ; y2 = h @ W2   (fp16 tensor cores)
    {
        dim3 g1(D1C / 128, (N_NODESC + 127) / 128);
        gemm1_k<<<g1, 256>>>(b1);
        dim3 g2(D2C / 64, (N_NODESC + 127) / 128);
        gemm2_k<<<g2, 256>>>();
    }

    // Layer 2 aggregation at 64 channels (fp16 gather) + fused final epilogue
    n2h2_k<<<(N_HEDGESC + 15) / 16, 256>>>();
    h2n2_k<<<(N_NODESC + 15) / 16, 256>>>(b2, out);
}